// round 1
// baseline (speedup 1.0000x reference)
#include <cuda_runtime.h>
#include <math.h>

// Problem dims
#define NL   8
#define NB   2
#define NT   1024
#define NC   1024
#define NH   16
#define NHD  64
#define NV   50257
#define NTOK 2048        // NB*NT
#define C3   3072        // 3*NC
#define C4   4096        // 4*NC

// ---------------- scratch (static device globals; no allocation) -------------
__device__ float g_x  [NTOK * NC];              // residual stream
__device__ float g_h  [NTOK * NC];              // layernorm output
__device__ float g_qkv[NTOK * C3];              // qkv projections
__device__ float g_att[(size_t)NB * NH * NT * NT]; // attention scores (134 MB)
__device__ float g_y  [NTOK * NC];              // attention output
__device__ float g_mlp[NTOK * C4];              // mlp hidden

// ---------------- block reductions (256 threads) ----------------------------
__device__ __forceinline__ float block_sum(float v) {
    __shared__ float sh[8];
    int lane = threadIdx.x & 31, w = threadIdx.x >> 5;
#pragma unroll
    for (int o = 16; o; o >>= 1) v += __shfl_xor_sync(0xffffffffu, v, o);
    if (lane == 0) sh[w] = v;
    __syncthreads();
    v = sh[0] + sh[1] + sh[2] + sh[3] + sh[4] + sh[5] + sh[6] + sh[7];
    __syncthreads();
    return v;
}

__device__ __forceinline__ float block_max(float v) {
    __shared__ float sh[8];
    int lane = threadIdx.x & 31, w = threadIdx.x >> 5;
#pragma unroll
    for (int o = 16; o; o >>= 1) v = fmaxf(v, __shfl_xor_sync(0xffffffffu, v, o));
    if (lane == 0) sh[w] = v;
    __syncthreads();
    v = fmaxf(fmaxf(fmaxf(sh[0], sh[1]), fmaxf(sh[2], sh[3])),
              fmaxf(fmaxf(sh[4], sh[5]), fmaxf(sh[6], sh[7])));
    __syncthreads();
    return v;
}

// ---------------- embedding --------------------------------------------------
__global__ void embed_kernel(const int* __restrict__ ids,
                             const float* __restrict__ wte,
                             const float* __restrict__ wpe,
                             float* __restrict__ x) {
    int tok = blockIdx.x;              // 0..2047
    int t   = tok & (NT - 1);
    int id  = ids[tok];
    const float* src = wte + (size_t)id * NC;
    const float* pp  = wpe + (size_t)t * NC;
    float* dst = x + (size_t)tok * NC;
    for (int c = threadIdx.x; c < NC; c += blockDim.x)
        dst[c] = src[c] + pp[c];
}

// ---------------- layernorm (one block per row, 256 threads) -----------------
__global__ void __launch_bounds__(256) ln_kernel(const float* __restrict__ x,
                                                 const float* __restrict__ w,
                                                 const float* __restrict__ b,
                                                 float* __restrict__ o) {
    int row = blockIdx.x, tid = threadIdx.x;
    const float* xr = x + (size_t)row * NC;
    float v[4]; float s = 0.f;
#pragma unroll
    for (int i = 0; i < 4; i++) { v[i] = xr[tid + 256 * i]; s += v[i]; }
    s = block_sum(s);
    float mean = s * (1.f / NC);
    float s2 = 0.f;
#pragma unroll
    for (int i = 0; i < 4; i++) { float d = v[i] - mean; s2 += d * d; }
    s2 = block_sum(s2);
    float rstd = rsqrtf(s2 * (1.f / NC) + 1e-5f);
    float* orow = o + (size_t)row * NC;
#pragma unroll
    for (int i = 0; i < 4; i++) {
        int c = tid + 256 * i;
        orow[c] = (v[i] - mean) * rstd * w[c] + b[c];
    }
}

// ---------------- SGEMM NN: D = epilogue(A[M,K] @ B[K,N] + bias) -------------
// EPI 0: store   1: residual add (D += ...)   2: exact GELU
// Requires: M%128==0, N%128==0, K%8==0 (true for all NN calls here)
template <int EPI>
__global__ void __launch_bounds__(256, 2) sgemm_nn(const float* __restrict__ A,
                                                   const float* __restrict__ B,
                                                   const float* __restrict__ bias,
                                                   float* __restrict__ D,
                                                   int M, int N, int K) {
    __shared__ float As[8][128];
    __shared__ float Bs[8][128];
    const int tid = threadIdx.x;
    const int bx = blockIdx.x, by = blockIdx.y;
    const int tr = tid >> 4, tc = tid & 15;
    const int arow = tid >> 1, acol = (tid & 1) << 2;
    const int brow = tid >> 5, bcol = (tid & 31) << 2;
    const float* Ap = A + (size_t)(by * 128 + arow) * K + acol;
    const float* Bp = B + (size_t)brow * N + bx * 128 + bcol;

    float acc[8][8];
#pragma unroll
    for (int i = 0; i < 8; i++)
#pragma unroll
        for (int j = 0; j < 8; j++) acc[i][j] = 0.f;

    for (int k0 = 0; k0 < K; k0 += 8) {
        float4 av = *reinterpret_cast<const float4*>(Ap + k0);
        float4 bv = *reinterpret_cast<const float4*>(Bp + (size_t)k0 * N);
        As[acol + 0][arow] = av.x; As[acol + 1][arow] = av.y;
        As[acol + 2][arow] = av.z; As[acol + 3][arow] = av.w;
        *reinterpret_cast<float4*>(&Bs[brow][bcol]) = bv;
        __syncthreads();
#pragma unroll
        for (int kk = 0; kk < 8; kk++) {
            float4 a0 = *reinterpret_cast<const float4*>(&As[kk][tr * 8]);
            float4 a1 = *reinterpret_cast<const float4*>(&As[kk][tr * 8 + 4]);
            float4 b0 = *reinterpret_cast<const float4*>(&Bs[kk][tc * 8]);
            float4 b1 = *reinterpret_cast<const float4*>(&Bs[kk][tc * 8 + 4]);
            float ar[8] = {a0.x, a0.y, a0.z, a0.w, a1.x, a1.y, a1.z, a1.w};
            float br[8] = {b0.x, b0.y, b0.z, b0.w, b1.x, b1.y, b1.z, b1.w};
#pragma unroll
            for (int i = 0; i < 8; i++)
#pragma unroll
                for (int j = 0; j < 8; j++) acc[i][j] += ar[i] * br[j];
        }
        __syncthreads();
    }

    const int row0 = by * 128 + tr * 8;
    const int col0 = bx * 128 + tc * 8;
#pragma unroll
    for (int i = 0; i < 8; i++) {
        float* drow = D + (size_t)(row0 + i) * N + col0;
#pragma unroll
        for (int j = 0; j < 8; j++) {
            float v = acc[i][j] + bias[col0 + j];
            if (EPI == 1) v += drow[j];
            if (EPI == 2) v = 0.5f * v * (1.f + erff(v * 0.70710678118654752f));
            drow[j] = v;
        }
    }
}

// ---------------- SGEMM NT: D = A[M,K] @ B[N,K]^T  (lm_head, no bias) --------
// N may be ragged (50257). K%8==0, M%128==0.
__global__ void __launch_bounds__(256, 2) sgemm_nt(const float* __restrict__ A,
                                                   const float* __restrict__ B,
                                                   float* __restrict__ D,
                                                   int M, int N, int K) {
    __shared__ float As[8][128];
    __shared__ float Bs[8][128];
    const int tid = threadIdx.x;
    const int bx = blockIdx.x, by = blockIdx.y;
    const int tr = tid >> 4, tc = tid & 15;
    const int arow = tid >> 1, acol = (tid & 1) << 2;
    const int nrow = tid >> 1, kcol = (tid & 1) << 2;
    const float* Ap = A + (size_t)(by * 128 + arow) * K + acol;
    const int gn = bx * 128 + nrow;
    const float* Bp = (gn < N) ? (B + (size_t)gn * K + kcol) : nullptr;

    float acc[8][8];
#pragma unroll
    for (int i = 0; i < 8; i++)
#pragma unroll
        for (int j = 0; j < 8; j++) acc[i][j] = 0.f;

    for (int k0 = 0; k0 < K; k0 += 8) {
        float4 av = *reinterpret_cast<const float4*>(Ap + k0);
        float4 bv = make_float4(0.f, 0.f, 0.f, 0.f);
        if (Bp) bv = *reinterpret_cast<const float4*>(Bp + k0);
        As[acol + 0][arow] = av.x; As[acol + 1][arow] = av.y;
        As[acol + 2][arow] = av.z; As[acol + 3][arow] = av.w;
        Bs[kcol + 0][nrow] = bv.x; Bs[kcol + 1][nrow] = bv.y;
        Bs[kcol + 2][nrow] = bv.z; Bs[kcol + 3][nrow] = bv.w;
        __syncthreads();
#pragma unroll
        for (int kk = 0; kk < 8; kk++) {
            float4 a0 = *reinterpret_cast<const float4*>(&As[kk][tr * 8]);
            float4 a1 = *reinterpret_cast<const float4*>(&As[kk][tr * 8 + 4]);
            float4 b0 = *reinterpret_cast<const float4*>(&Bs[kk][tc * 8]);
            float4 b1 = *reinterpret_cast<const float4*>(&Bs[kk][tc * 8 + 4]);
            float ar[8] = {a0.x, a0.y, a0.z, a0.w, a1.x, a1.y, a1.z, a1.w};
            float br[8] = {b0.x, b0.y, b0.z, b0.w, b1.x, b1.y, b1.z, b1.w};
#pragma unroll
            for (int i = 0; i < 8; i++)
#pragma unroll
                for (int j = 0; j < 8; j++) acc[i][j] += ar[i] * br[j];
        }
        __syncthreads();
    }

    const int row0 = by * 128 + tr * 8;
    const int col0 = bx * 128 + tc * 8;
#pragma unroll
    for (int i = 0; i < 8; i++) {
        float* drow = D + (size_t)(row0 + i) * N;
#pragma unroll
        for (int j = 0; j < 8; j++) {
            int c = col0 + j;
            if (c < N) drow[c] = acc[i][j];
        }
    }
}

// ---------------- attention scores: att = (Q @ K^T) * scale ------------------
// grid: (ktile=16, qtile=16, bh=32), 256 threads, 64x64 tile, hd=64 inner
__global__ void __launch_bounds__(256) attn_scores(const float* __restrict__ qkv,
                                                   float* __restrict__ att) {
    const int bh = blockIdx.z, b = bh >> 4, h = bh & 15;
    const int qt = blockIdx.y, kt = blockIdx.x;
    __shared__ float Qs[64][65];
    __shared__ float Ks[64][65];
    const int tid = threadIdx.x;
    const int lrow = tid >> 2, d0 = (tid & 3) << 4;
    const float* qp = qkv + (size_t)(b * NT + qt * 64 + lrow) * C3 + h * NHD + d0;
    const float* kp = qkv + (size_t)(b * NT + kt * 64 + lrow) * C3 + NC + h * NHD + d0;
#pragma unroll
    for (int i = 0; i < 4; i++) {
        float4 qv = *reinterpret_cast<const float4*>(qp + 4 * i);
        float4 kv = *reinterpret_cast<const float4*>(kp + 4 * i);
        Qs[lrow][d0 + 4 * i + 0] = qv.x; Qs[lrow][d0 + 4 * i + 1] = qv.y;
        Qs[lrow][d0 + 4 * i + 2] = qv.z; Qs[lrow][d0 + 4 * i + 3] = qv.w;
        Ks[lrow][d0 + 4 * i + 0] = kv.x; Ks[lrow][d0 + 4 * i + 1] = kv.y;
        Ks[lrow][d0 + 4 * i + 2] = kv.z; Ks[lrow][d0 + 4 * i + 3] = kv.w;
    }
    __syncthreads();
    const int tr = tid >> 4, tc = tid & 15;
    float acc[4][4] = {};
#pragma unroll
    for (int d = 0; d < 64; d++) {
        float ar[4], br[4];
#pragma unroll
        for (int i = 0; i < 4; i++) ar[i] = Qs[tr * 4 + i][d];
#pragma unroll
        for (int j = 0; j < 4; j++) br[j] = Ks[tc * 4 + j][d];
#pragma unroll
        for (int i = 0; i < 4; i++)
#pragma unroll
            for (int j = 0; j < 4; j++) acc[i][j] += ar[i] * br[j];
    }
#pragma unroll
    for (int i = 0; i < 4; i++) {
        float* dst = att + ((size_t)bh * NT + qt * 64 + tr * 4 + i) * NT + kt * 64 + tc * 4;
#pragma unroll
        for (int j = 0; j < 4; j++) dst[j] = acc[i][j] * 0.125f;  // 1/sqrt(64)
    }
}

// ---------------- softmax over rows of att (length T=1024) -------------------
__global__ void __launch_bounds__(256) softmax_kernel(float* __restrict__ att) {
    float* p = att + (size_t)blockIdx.x * NT;
    int tid = threadIdx.x;
    float v[4]; float m = -1e30f;
#pragma unroll
    for (int i = 0; i < 4; i++) { v[i] = p[tid + 256 * i]; m = fmaxf(m, v[i]); }
    m = block_max(m);
    float s = 0.f;
#pragma unroll
    for (int i = 0; i < 4; i++) { v[i] = __expf(v[i] - m); s += v[i]; }
    s = block_sum(s);
    float inv = 1.f / s;
#pragma unroll
    for (int i = 0; i < 4; i++) p[tid + 256 * i] = v[i] * inv;
}

// ---------------- attention output: y = att @ V ------------------------------
// grid: (qtile=16, bh=32), 64 q-rows x 64 head-dims, K loop over T in 64 chunks
__global__ void __launch_bounds__(256) attn_av(const float* __restrict__ att,
                                               const float* __restrict__ qkv,
                                               float* __restrict__ y) {
    const int bh = blockIdx.y, b = bh >> 4, h = bh & 15;
    const int qt = blockIdx.x;
    __shared__ float Ps[64][68];
    __shared__ float Vs[64][68];
    const int tid = threadIdx.x;
    const int lrow = tid >> 2, c0 = (tid & 3) << 4;
    const int tr = tid >> 4, tc = tid & 15;
    float acc[4][4] = {};
    for (int kt = 0; kt < 16; kt++) {
        const float* pp = att + ((size_t)bh * NT + qt * 64 + lrow) * NT + kt * 64 + c0;
        const float* vp = qkv + (size_t)(b * NT + kt * 64 + lrow) * C3 + 2 * NC + h * NHD + c0;
#pragma unroll
        for (int i = 0; i < 4; i++) {
            float4 pv = *reinterpret_cast<const float4*>(pp + 4 * i);
            float4 vv = *reinterpret_cast<const float4*>(vp + 4 * i);
            Ps[lrow][c0 + 4 * i + 0] = pv.x; Ps[lrow][c0 + 4 * i + 1] = pv.y;
            Ps[lrow][c0 + 4 * i + 2] = pv.z; Ps[lrow][c0 + 4 * i + 3] = pv.w;
            Vs[lrow][c0 + 4 * i + 0] = vv.x; Vs[lrow][c0 + 4 * i + 1] = vv.y;
            Vs[lrow][c0 + 4 * i + 2] = vv.z; Vs[lrow][c0 + 4 * i + 3] = vv.w;
        }
        __syncthreads();
#pragma unroll
        for (int kk = 0; kk < 64; kk++) {
            float ar[4], br[4];
#pragma unroll
            for (int i = 0; i < 4; i++) ar[i] = Ps[tr * 4 + i][kk];
            float4 bv = *reinterpret_cast<const float4*>(&Vs[kk][tc * 4]);
            br[0] = bv.x; br[1] = bv.y; br[2] = bv.z; br[3] = bv.w;
#pragma unroll
            for (int i = 0; i < 4; i++)
#pragma unroll
                for (int j = 0; j < 4; j++) acc[i][j] += ar[i] * br[j];
        }
        __syncthreads();
    }
#pragma unroll
    for (int i = 0; i < 4; i++) {
        float* dst = y + (size_t)(b * NT + qt * 64 + tr * 4 + i) * NC + h * NHD + tc * 4;
#pragma unroll
        for (int j = 0; j < 4; j++) dst[j] = acc[i][j];
    }
}

// ---------------- host orchestration -----------------------------------------
extern "C" void kernel_launch(void* const* d_in, const int* in_sizes, int n_in,
                              void* d_out, int out_size) {
    const int*   ids    = (const int*)  d_in[0];
    const float* wte    = (const float*)d_in[1];
    const float* wpe    = (const float*)d_in[2];
    const float* ln1_w  = (const float*)d_in[3];
    const float* ln1_b  = (const float*)d_in[4];
    const float* attn_w = (const float*)d_in[5];
    const float* attn_b = (const float*)d_in[6];
    const float* proj_w = (const float*)d_in[7];
    const float* proj_b = (const float*)d_in[8];
    const float* ln2_w  = (const float*)d_in[9];
    const float* ln2_b  = (const float*)d_in[10];
    const float* fc_w   = (const float*)d_in[11];
    const float* fc_b   = (const float*)d_in[12];
    const float* fc2_w  = (const float*)d_in[13];
    const float* fc2_b  = (const float*)d_in[14];
    const float* lnf_w  = (const float*)d_in[15];
    const float* lnf_b  = (const float*)d_in[16];
    float* out = (float*)d_out;

    float *x, *h, *qkv, *att, *y, *mlp;
    cudaGetSymbolAddress((void**)&x,   g_x);
    cudaGetSymbolAddress((void**)&h,   g_h);
    cudaGetSymbolAddress((void**)&qkv, g_qkv);
    cudaGetSymbolAddress((void**)&att, g_att);
    cudaGetSymbolAddress((void**)&y,   g_y);
    cudaGetSymbolAddress((void**)&mlp, g_mlp);

    embed_kernel<<<NTOK, 256>>>(ids, wte, wpe, x);

    for (int l = 0; l < NL; l++) {
        // --- attention block ---
        ln_kernel<<<NTOK, 256>>>(x, ln1_w + (size_t)l * NC, ln1_b + (size_t)l * NC, h);
        sgemm_nn<0><<<dim3(C3 / 128, NTOK / 128), 256>>>(
            h, attn_w + (size_t)l * NC * C3, attn_b + (size_t)l * C3, qkv,
            NTOK, C3, NC);
        attn_scores<<<dim3(NT / 64, NT / 64, NB * NH), 256>>>(qkv, att);
        softmax_kernel<<<NB * NH * NT, 256>>>(att);
        attn_av<<<dim3(NT / 64, NB * NH), 256>>>(att, qkv, y);
        sgemm_nn<1><<<dim3(NC / 128, NTOK / 128), 256>>>(
            y, proj_w + (size_t)l * NC * NC, proj_b + (size_t)l * NC, x,
            NTOK, NC, NC);
        // --- MLP block ---
        ln_kernel<<<NTOK, 256>>>(x, ln2_w + (size_t)l * NC, ln2_b + (size_t)l * NC, h);
        sgemm_nn<2><<<dim3(C4 / 128, NTOK / 128), 256>>>(
            h, fc_w + (size_t)l * NC * C4, fc_b + (size_t)l * C4, mlp,
            NTOK, C4, NC);
        sgemm_nn<1><<<dim3(NC / 128, NTOK / 128), 256>>>(
            mlp, fc2_w + (size_t)l * C4 * NC, fc2_b + (size_t)l * NC, x,
            NTOK, NC, C4);
    }

    // final LN + tied lm_head
    ln_kernel<<<NTOK, 256>>>(x, lnf_w, lnf_b, h);
    sgemm_nt<<<dim3((NV + 127) / 128, NTOK / 128), 256>>>(h, wte, out, NTOK, NV, NC);
}

// round 3
// speedup vs baseline: 1.5184x; 1.5184x over previous
#include <cuda_runtime.h>
#include <math.h>
#include <stdint.h>

// Problem dims
#define NL   8
#define NB   2
#define NT   1024
#define NC   1024
#define NH   16
#define NHD  64
#define NV   50257
#define NTOK 2048        // NB*NT
#define C3   3072        // 3*NC
#define C4   4096        // 4*NC

// ---------------- scratch (static device globals; no allocation) -------------
__device__ float g_x  [NTOK * NC];
__device__ float g_h  [NTOK * NC];
__device__ float g_qkv[NTOK * C3];
__device__ float g_att[(size_t)NB * NH * NT * NT];
__device__ float g_y  [NTOK * NC];
__device__ float g_mlp[NTOK * C4];

// ---------------- helpers ----------------------------------------------------
__device__ __forceinline__ uint32_t f2tf32(float x) {
    uint32_t r;
    asm("cvt.rna.tf32.f32 %0, %1;" : "=r"(r) : "f"(x));
    return r;
}

__device__ __forceinline__ void mma_tf32(float* d, const uint32_t* a, const uint32_t* b) {
    asm volatile(
        "mma.sync.aligned.m16n8k8.row.col.f32.tf32.tf32.f32 "
        "{%0,%1,%2,%3}, {%4,%5,%6,%7}, {%8,%9}, {%0,%1,%2,%3};"
        : "+f"(d[0]), "+f"(d[1]), "+f"(d[2]), "+f"(d[3])
        : "r"(a[0]), "r"(a[1]), "r"(a[2]), "r"(a[3]), "r"(b[0]), "r"(b[1]));
}

__device__ __forceinline__ float block_sum(float v) {
    __shared__ float sh[8];
    int lane = threadIdx.x & 31, w = threadIdx.x >> 5;
#pragma unroll
    for (int o = 16; o; o >>= 1) v += __shfl_xor_sync(0xffffffffu, v, o);
    if (lane == 0) sh[w] = v;
    __syncthreads();
    v = sh[0] + sh[1] + sh[2] + sh[3] + sh[4] + sh[5] + sh[6] + sh[7];
    __syncthreads();
    return v;
}

__device__ __forceinline__ float block_max(float v) {
    __shared__ float sh[8];
    int lane = threadIdx.x & 31, w = threadIdx.x >> 5;
#pragma unroll
    for (int o = 16; o; o >>= 1) v = fmaxf(v, __shfl_xor_sync(0xffffffffu, v, o));
    if (lane == 0) sh[w] = v;
    __syncthreads();
    v = fmaxf(fmaxf(fmaxf(sh[0], sh[1]), fmaxf(sh[2], sh[3])),
              fmaxf(fmaxf(sh[4], sh[5]), fmaxf(sh[6], sh[7])));
    __syncthreads();
    return v;
}

// ---------------- embedding --------------------------------------------------
__global__ void embed_kernel(const int* __restrict__ ids,
                             const float* __restrict__ wte,
                             const float* __restrict__ wpe,
                             float* __restrict__ x) {
    int tok = blockIdx.x;
    int t   = tok & (NT - 1);
    int id  = ids[tok];
    const float* src = wte + (size_t)id * NC;
    const float* pp  = wpe + (size_t)t * NC;
    float* dst = x + (size_t)tok * NC;
    for (int c = threadIdx.x; c < NC; c += blockDim.x)
        dst[c] = src[c] + pp[c];
}

// ---------------- layernorm --------------------------------------------------
__global__ void __launch_bounds__(256) ln_kernel(const float* __restrict__ x,
                                                 const float* __restrict__ w,
                                                 const float* __restrict__ b,
                                                 float* __restrict__ o) {
    int row = blockIdx.x, tid = threadIdx.x;
    const float* xr = x + (size_t)row * NC;
    float v[4]; float s = 0.f;
#pragma unroll
    for (int i = 0; i < 4; i++) { v[i] = xr[tid + 256 * i]; s += v[i]; }
    s = block_sum(s);
    float mean = s * (1.f / NC);
    float s2 = 0.f;
#pragma unroll
    for (int i = 0; i < 4; i++) { float d = v[i] - mean; s2 += d * d; }
    s2 = block_sum(s2);
    float rstd = rsqrtf(s2 * (1.f / NC) + 1e-5f);
    float* orow = o + (size_t)row * NC;
#pragma unroll
    for (int i = 0; i < 4; i++) {
        int c = tid + 256 * i;
        orow[c] = (v[i] - mean) * rstd * w[c] + b[c];
    }
}

// =============================================================================
// TF32 tensor-core GEMM, 128x128x16 tile, 256 threads (8 warps, 2x4),
// warp tile 64x32 (4x4 grid of m16n8k8). Operands staged into smem in
// MMA-fragment layout, pre-converted to tf32.
// EPI 0: store  1: residual add  2: exact GELU
// Fragment index maps (verified vs PTX ISA):
//   A (16x8, row r, col c): idx = (r&7)*16 + (c&3)*4 + (r>>3) + 2*(c>>2)
//   B (8x8, k, n):          idx = n*8 + (k&3)*2 + (k>>2)
// =============================================================================

template <int EPI>
__global__ void __launch_bounds__(256) tgemm_nn(const float* __restrict__ A,
                                                const float* __restrict__ B,
                                                const float* __restrict__ bias,
                                                float* __restrict__ D,
                                                int M, int N, int K) {
    __shared__ uint32_t smA[2][2048];
    __shared__ uint32_t smB[2][2048];

    const int tid  = threadIdx.x;
    const int lane = tid & 31;
    const int warp = tid >> 5;
    const int wm   = warp >> 2;     // 0..1
    const int wn   = warp & 3;      // 0..3
    const int bx = blockIdx.x, by = blockIdx.y;

    // ---- A staging: thread covers row r=tid>>1, kstep=tid&1, 8 k-cols
    const int ar  = tid >> 1;
    const int aks = tid & 1;
    const int art = ar & 15;
    const int abase = ((aks * 8 + (ar >> 4)) * 128) + (art & 7) * 16 + (art >> 3);
    const float* Ag = A + (size_t)(by * 128 + ar) * K + (aks << 3);

    // ---- B staging: thread covers k-row kr=tid>>4, 8 n-cols
    const int bkr = tid >> 4;
    const int bks = bkr >> 3;
    const int bkw = bkr & 7;
    const int bbase = ((bks * 16 + (tid & 15)) * 64) + (bkw & 3) * 2 + (bkw >> 2);
    const float* Bg = B + (size_t)bkr * N + bx * 128 + (tid & 15) * 8;

    float acc[4][4][4];
#pragma unroll
    for (int i = 0; i < 4; i++)
#pragma unroll
        for (int j = 0; j < 4; j++)
#pragma unroll
            for (int r = 0; r < 4; r++) acc[i][j][r] = 0.f;

    const int KT = K >> 4;
    float4 pa0, pa1, pb0, pb1;

    pa0 = *reinterpret_cast<const float4*>(Ag);
    pa1 = *reinterpret_cast<const float4*>(Ag + 4);
    pb0 = *reinterpret_cast<const float4*>(Bg);
    pb1 = *reinterpret_cast<const float4*>(Bg + 4);
    {
        float va[8] = {pa0.x, pa0.y, pa0.z, pa0.w, pa1.x, pa1.y, pa1.z, pa1.w};
        float vb[8] = {pb0.x, pb0.y, pb0.z, pb0.w, pb1.x, pb1.y, pb1.z, pb1.w};
#pragma unroll
        for (int j = 0; j < 8; j++) {
            smA[0][abase + (j & 3) * 4 + (j >> 2) * 2] = f2tf32(va[j]);
            smB[0][bbase + j * 8]                      = f2tf32(vb[j]);
        }
    }
    __syncthreads();

    for (int kt = 0; kt < KT; kt++) {
        const int s = kt & 1;
        if (kt + 1 < KT) {
            const float* Ap = Ag + (size_t)(kt + 1) * 16;
            const float* Bp = Bg + (size_t)(kt + 1) * 16 * N;
            pa0 = *reinterpret_cast<const float4*>(Ap);
            pa1 = *reinterpret_cast<const float4*>(Ap + 4);
            pb0 = *reinterpret_cast<const float4*>(Bp);
            pb1 = *reinterpret_cast<const float4*>(Bp + 4);
        }
#pragma unroll
        for (int ks = 0; ks < 2; ks++) {
            uint32_t af[4][4], bf[4][2];
#pragma unroll
            for (int mt = 0; mt < 4; mt++)
                *reinterpret_cast<uint4*>(af[mt]) =
                    *reinterpret_cast<const uint4*>(&smA[s][(ks * 8 + wm * 4 + mt) * 128 + lane * 4]);
#pragma unroll
            for (int nt = 0; nt < 4; nt++)
                *reinterpret_cast<uint2*>(bf[nt]) =
                    *reinterpret_cast<const uint2*>(&smB[s][(ks * 16 + wn * 4 + nt) * 64 + lane * 2]);
#pragma unroll
            for (int mt = 0; mt < 4; mt++)
#pragma unroll
                for (int nt = 0; nt < 4; nt++)
                    mma_tf32(acc[mt][nt], af[mt], bf[nt]);
        }
        if (kt + 1 < KT) {
            float va[8] = {pa0.x, pa0.y, pa0.z, pa0.w, pa1.x, pa1.y, pa1.z, pa1.w};
            float vb[8] = {pb0.x, pb0.y, pb0.z, pb0.w, pb1.x, pb1.y, pb1.z, pb1.w};
            const int ns = s ^ 1;
#pragma unroll
            for (int j = 0; j < 8; j++) {
                smA[ns][abase + (j & 3) * 4 + (j >> 2) * 2] = f2tf32(va[j]);
                smB[ns][bbase + j * 8]                      = f2tf32(vb[j]);
            }
        }
        __syncthreads();
    }

#pragma unroll
    for (int mt = 0; mt < 4; mt++) {
        const int row0 = by * 128 + wm * 64 + mt * 16 + (lane >> 2);
#pragma unroll
        for (int nt = 0; nt < 4; nt++) {
            const int col0 = bx * 128 + wn * 32 + nt * 8 + (lane & 3) * 2;
#pragma unroll
            for (int half = 0; half < 2; half++) {
                float* drow = D + (size_t)(row0 + half * 8) * N + col0;
                float v0 = acc[mt][nt][half * 2 + 0] + bias[col0];
                float v1 = acc[mt][nt][half * 2 + 1] + bias[col0 + 1];
                if (EPI == 1) { v0 += drow[0]; v1 += drow[1]; }
                if (EPI == 2) {
                    v0 = 0.5f * v0 * (1.f + erff(v0 * 0.70710678118654752f));
                    v1 = 0.5f * v1 * (1.f + erff(v1 * 0.70710678118654752f));
                }
                drow[0] = v0; drow[1] = v1;
            }
        }
    }
}

// NT variant: D = A[M,K] @ B[N,K]^T, ragged N (lm_head), no bias
__global__ void __launch_bounds__(256) tgemm_nt(const float* __restrict__ A,
                                                const float* __restrict__ B,
                                                float* __restrict__ D,
                                                int M, int N, int K) {
    __shared__ uint32_t smA[2][2048];
    __shared__ uint32_t smB[2][2048];

    const int tid  = threadIdx.x;
    const int lane = tid & 31;
    const int warp = tid >> 5;
    const int wm   = warp >> 2;
    const int wn   = warp & 3;
    const int bx = blockIdx.x, by = blockIdx.y;

    const int ar  = tid >> 1;
    const int aks = tid & 1;
    const int art = ar & 15;
    const int abase = ((aks * 8 + (ar >> 4)) * 128) + (art & 7) * 16 + (art >> 3);
    const float* Ag = A + (size_t)(by * 128 + ar) * K + (aks << 3);

    // B: thread covers n-row nr=tid>>1, kstep=tid&1, 8 k-cols
    const int nr  = tid >> 1;
    const int nks = tid & 1;
    const int gn  = bx * 128 + nr;
    const bool nok = (gn < N);
    const int bbase = ((nks * 16 + (nr >> 3)) * 64) + (nr & 7) * 8;
    const float* Bg = nok ? (B + (size_t)gn * K + (nks << 3)) : A;  // dummy safe ptr

    float acc[4][4][4];
#pragma unroll
    for (int i = 0; i < 4; i++)
#pragma unroll
        for (int j = 0; j < 4; j++)
#pragma unroll
            for (int r = 0; r < 4; r++) acc[i][j][r] = 0.f;

    const int KT = K >> 4;
    float4 pa0, pa1, pb0, pb1;

    pa0 = *reinterpret_cast<const float4*>(Ag);
    pa1 = *reinterpret_cast<const float4*>(Ag + 4);
    pb0 = *reinterpret_cast<const float4*>(Bg);
    pb1 = *reinterpret_cast<const float4*>(Bg + 4);
    if (!nok) { pb0 = make_float4(0, 0, 0, 0); pb1 = pb0; }
    {
        float va[8] = {pa0.x, pa0.y, pa0.z, pa0.w, pa1.x, pa1.y, pa1.z, pa1.w};
        float vb[8] = {pb0.x, pb0.y, pb0.z, pb0.w, pb1.x, pb1.y, pb1.z, pb1.w};
#pragma unroll
        for (int j = 0; j < 8; j++) {
            smA[0][abase + (j & 3) * 4 + (j >> 2) * 2] = f2tf32(va[j]);
            smB[0][bbase + (j & 3) * 2 + (j >> 2)]     = f2tf32(vb[j]);   // FIXED: k-term *2
        }
    }
    __syncthreads();

    for (int kt = 0; kt < KT; kt++) {
        const int s = kt & 1;
        if (kt + 1 < KT) {
            const float* Ap = Ag + (size_t)(kt + 1) * 16;
            const float* Bp = Bg + (size_t)(kt + 1) * 16;
            pa0 = *reinterpret_cast<const float4*>(Ap);
            pa1 = *reinterpret_cast<const float4*>(Ap + 4);
            pb0 = *reinterpret_cast<const float4*>(Bp);
            pb1 = *reinterpret_cast<const float4*>(Bp + 4);
            if (!nok) { pb0 = make_float4(0, 0, 0, 0); pb1 = pb0; }
        }
#pragma unroll
        for (int ks = 0; ks < 2; ks++) {
            uint32_t af[4][4], bf[4][2];
#pragma unroll
            for (int mt = 0; mt < 4; mt++)
                *reinterpret_cast<uint4*>(af[mt]) =
                    *reinterpret_cast<const uint4*>(&smA[s][(ks * 8 + wm * 4 + mt) * 128 + lane * 4]);
#pragma unroll
            for (int nt = 0; nt < 4; nt++)
                *reinterpret_cast<uint2*>(bf[nt]) =
                    *reinterpret_cast<const uint2*>(&smB[s][(ks * 16 + wn * 4 + nt) * 64 + lane * 2]);
#pragma unroll
            for (int mt = 0; mt < 4; mt++)
#pragma unroll
                for (int nt = 0; nt < 4; nt++)
                    mma_tf32(acc[mt][nt], af[mt], bf[nt]);
        }
        if (kt + 1 < KT) {
            float va[8] = {pa0.x, pa0.y, pa0.z, pa0.w, pa1.x, pa1.y, pa1.z, pa1.w};
            float vb[8] = {pb0.x, pb0.y, pb0.z, pb0.w, pb1.x, pb1.y, pb1.z, pb1.w};
            const int ns = s ^ 1;
#pragma unroll
            for (int j = 0; j < 8; j++) {
                smA[ns][abase + (j & 3) * 4 + (j >> 2) * 2] = f2tf32(va[j]);
                smB[ns][bbase + (j & 3) * 2 + (j >> 2)]     = f2tf32(vb[j]);   // FIXED
            }
        }
        __syncthreads();
    }

#pragma unroll
    for (int mt = 0; mt < 4; mt++) {
        const int row0 = by * 128 + wm * 64 + mt * 16 + (lane >> 2);
#pragma unroll
        for (int nt = 0; nt < 4; nt++) {
            const int col0 = bx * 128 + wn * 32 + nt * 8 + (lane & 3) * 2;
#pragma unroll
            for (int half = 0; half < 2; half++) {
                float* drow = D + (size_t)(row0 + half * 8) * N;
                if (col0 < N)     drow[col0]     = acc[mt][nt][half * 2 + 0];
                if (col0 + 1 < N) drow[col0 + 1] = acc[mt][nt][half * 2 + 1];
            }
        }
    }
}

// ---------------- attention scores: att = (Q @ K^T) * scale (fp32) -----------
__global__ void __launch_bounds__(256) attn_scores(const float* __restrict__ qkv,
                                                   float* __restrict__ att) {
    const int bh = blockIdx.z, b = bh >> 4, h = bh & 15;
    const int qt = blockIdx.y, kt = blockIdx.x;
    __shared__ float Qs[64][65];
    __shared__ float Ks[64][65];
    const int tid = threadIdx.x;
    const int lrow = tid >> 2, d0 = (tid & 3) << 4;
    const float* qp = qkv + (size_t)(b * NT + qt * 64 + lrow) * C3 + h * NHD + d0;
    const float* kp = qkv + (size_t)(b * NT + kt * 64 + lrow) * C3 + NC + h * NHD + d0;
#pragma unroll
    for (int i = 0; i < 4; i++) {
        float4 qv = *reinterpret_cast<const float4*>(qp + 4 * i);
        float4 kv = *reinterpret_cast<const float4*>(kp + 4 * i);
        Qs[lrow][d0 + 4 * i + 0] = qv.x; Qs[lrow][d0 + 4 * i + 1] = qv.y;
        Qs[lrow][d0 + 4 * i + 2] = qv.z; Qs[lrow][d0 + 4 * i + 3] = qv.w;
        Ks[lrow][d0 + 4 * i + 0] = kv.x; Ks[lrow][d0 + 4 * i + 1] = kv.y;
        Ks[lrow][d0 + 4 * i + 2] = kv.z; Ks[lrow][d0 + 4 * i + 3] = kv.w;
    }
    __syncthreads();
    const int tr = tid >> 4, tc = tid & 15;
    float acc[4][4] = {};
#pragma unroll
    for (int d = 0; d < 64; d++) {
        float ar[4], br[4];
#pragma unroll
        for (int i = 0; i < 4; i++) ar[i] = Qs[tr * 4 + i][d];
#pragma unroll
        for (int j = 0; j < 4; j++) br[j] = Ks[tc * 4 + j][d];
#pragma unroll
        for (int i = 0; i < 4; i++)
#pragma unroll
            for (int j = 0; j < 4; j++) acc[i][j] += ar[i] * br[j];
    }
#pragma unroll
    for (int i = 0; i < 4; i++) {
        float* dst = att + ((size_t)bh * NT + qt * 64 + tr * 4 + i) * NT + kt * 64 + tc * 4;
#pragma unroll
        for (int j = 0; j < 4; j++) dst[j] = acc[i][j] * 0.125f;
    }
}

// ---------------- softmax ----------------------------------------------------
__global__ void __launch_bounds__(256) softmax_kernel(float* __restrict__ att) {
    float* p = att + (size_t)blockIdx.x * NT;
    int tid = threadIdx.x;
    float v[4]; float m = -1e30f;
#pragma unroll
    for (int i = 0; i < 4; i++) { v[i] = p[tid + 256 * i]; m = fmaxf(m, v[i]); }
    m = block_max(m);
    float s = 0.f;
#pragma unroll
    for (int i = 0; i < 4; i++) { v[i] = __expf(v[i] - m); s += v[i]; }
    s = block_sum(s);
    float inv = 1.f / s;
#pragma unroll
    for (int i = 0; i < 4; i++) p[tid + 256 * i] = v[i] * inv;
}

// ---------------- attention output: y = att @ V (fp32) -----------------------
__global__ void __launch_bounds__(256) attn_av(const float* __restrict__ att,
                                               const float* __restrict__ qkv,
                                               float* __restrict__ y) {
    const int bh = blockIdx.y, b = bh >> 4, h = bh & 15;
    const int qt = blockIdx.x;
    __shared__ float Ps[64][68];
    __shared__ float Vs[64][68];
    const int tid = threadIdx.x;
    const int lrow = tid >> 2, c0 = (tid & 3) << 4;
    const int tr = tid >> 4, tc = tid & 15;
    float acc[4][4] = {};
    for (int kt = 0; kt < 16; kt++) {
        const float* pp = att + ((size_t)bh * NT + qt * 64 + lrow) * NT + kt * 64 + c0;
        const float* vp = qkv + (size_t)(b * NT + kt * 64 + lrow) * C3 + 2 * NC + h * NHD + c0;
#pragma unroll
        for (int i = 0; i < 4; i++) {
            float4 pv = *reinterpret_cast<const float4*>(pp + 4 * i);
            float4 vv = *reinterpret_cast<const float4*>(vp + 4 * i);
            Ps[lrow][c0 + 4 * i + 0] = pv.x; Ps[lrow][c0 + 4 * i + 1] = pv.y;
            Ps[lrow][c0 + 4 * i + 2] = pv.z; Ps[lrow][c0 + 4 * i + 3] = pv.w;
            Vs[lrow][c0 + 4 * i + 0] = vv.x; Vs[lrow][c0 + 4 * i + 1] = vv.y;
            Vs[lrow][c0 + 4 * i + 2] = vv.z; Vs[lrow][c0 + 4 * i + 3] = vv.w;
        }
        __syncthreads();
#pragma unroll
        for (int kk = 0; kk < 64; kk++) {
            float ar[4], br[4];
#pragma unroll
            for (int i = 0; i < 4; i++) ar[i] = Ps[tr * 4 + i][kk];
            float4 bv = *reinterpret_cast<const float4*>(&Vs[kk][tc * 4]);
            br[0] = bv.x; br[1] = bv.y; br[2] = bv.z; br[3] = bv.w;
#pragma unroll
            for (int i = 0; i < 4; i++)
#pragma unroll
                for (int j = 0; j < 4; j++) acc[i][j] += ar[i] * br[j];
        }
        __syncthreads();
    }
#pragma unroll
    for (int i = 0; i < 4; i++) {
        float* dst = y + (size_t)(b * NT + qt * 64 + tr * 4 + i) * NC + h * NHD + tc * 4;
#pragma unroll
        for (int j = 0; j < 4; j++) dst[j] = acc[i][j];
    }
}

// ---------------- host orchestration -----------------------------------------
extern "C" void kernel_launch(void* const* d_in, const int* in_sizes, int n_in,
                              void* d_out, int out_size) {
    const int*   ids    = (const int*)  d_in[0];
    const float* wte    = (const float*)d_in[1];
    const float* wpe    = (const float*)d_in[2];
    const float* ln1_w  = (const float*)d_in[3];
    const float* ln1_b  = (const float*)d_in[4];
    const float* attn_w = (const float*)d_in[5];
    const float* attn_b = (const float*)d_in[6];
    const float* proj_w = (const float*)d_in[7];
    const float* proj_b = (const float*)d_in[8];
    const float* ln2_w  = (const float*)d_in[9];
    const float* ln2_b  = (const float*)d_in[10];
    const float* fc_w   = (const float*)d_in[11];
    const float* fc_b   = (const float*)d_in[12];
    const float* fc2_w  = (const float*)d_in[13];
    const float* fc2_b  = (const float*)d_in[14];
    const float* lnf_w  = (const float*)d_in[15];
    const float* lnf_b  = (const float*)d_in[16];
    float* out = (float*)d_out;

    float *x, *h, *qkv, *att, *y, *mlp;
    cudaGetSymbolAddress((void**)&x,   g_x);
    cudaGetSymbolAddress((void**)&h,   g_h);
    cudaGetSymbolAddress((void**)&qkv, g_qkv);
    cudaGetSymbolAddress((void**)&att, g_att);
    cudaGetSymbolAddress((void**)&y,   g_y);
    cudaGetSymbolAddress((void**)&mlp, g_mlp);

    embed_kernel<<<NTOK, 256>>>(ids, wte, wpe, x);

    for (int l = 0; l < NL; l++) {
        ln_kernel<<<NTOK, 256>>>(x, ln1_w + (size_t)l * NC, ln1_b + (size_t)l * NC, h);
        tgemm_nn<0><<<dim3(C3 / 128, NTOK / 128), 256>>>(
            h, attn_w + (size_t)l * NC * C3, attn_b + (size_t)l * C3, qkv,
            NTOK, C3, NC);
        attn_scores<<<dim3(NT / 64, NT / 64, NB * NH), 256>>>(qkv, att);
        softmax_kernel<<<NB * NH * NT, 256>>>(att);
        attn_av<<<dim3(NT / 64, NB * NH), 256>>>(att, qkv, y);
        tgemm_nn<1><<<dim3(NC / 128, NTOK / 128), 256>>>(
            y, proj_w + (size_t)l * NC * NC, proj_b + (size_t)l * NC, x,
            NTOK, NC, NC);
        ln_kernel<<<NTOK, 256>>>(x, ln2_w + (size_t)l * NC, ln2_b + (size_t)l * NC, h);
        tgemm_nn<2><<<dim3(C4 / 128, NTOK / 128), 256>>>(
            h, fc_w + (size_t)l * NC * C4, fc_b + (size_t)l * C4, mlp,
            NTOK, C4, NC);
        tgemm_nn<1><<<dim3(NC / 128, NTOK / 128), 256>>>(
            mlp, fc2_w + (size_t)l * C4 * NC, fc2_b + (size_t)l * NC, x,
            NTOK, NC, C4);
    }

    ln_kernel<<<NTOK, 256>>>(x, lnf_w, lnf_b, h);
    tgemm_nt<<<dim3((NV + 127) / 128, NTOK / 128), 256>>>(h, wte, out, NTOK, NV, NC);
}

// round 5
// speedup vs baseline: 1.9479x; 1.2829x over previous
#include <cuda_runtime.h>
#include <cuda_fp16.h>
#include <math.h>
#include <stdint.h>

// Problem dims
#define NL   8
#define NB   2
#define NT   1024
#define NC   1024
#define NH   16
#define NHD  64
#define NV   50257
#define NTOK 2048
#define C3   3072
#define C4   4096

// ---------------- scratch ----------------------------------------------------
__device__ float g_x  [NTOK * NC];
__device__ float g_h  [NTOK * NC];
__device__ float g_qkv[NTOK * C3];
__device__ float g_att[(size_t)NB * NH * NT * NT];
__device__ float g_y  [NTOK * NC];
__device__ float g_mlp[NTOK * C4];

// ---------------- helpers ----------------------------------------------------
__device__ __forceinline__ uint32_t f2h2(float lo, float hi) {
    __half2 h = __floats2half2_rn(lo, hi);
    return *reinterpret_cast<uint32_t*>(&h);
}

__device__ __forceinline__ void mma_f16(float* d, const uint32_t* a, const uint32_t* b) {
    asm volatile(
        "mma.sync.aligned.m16n8k16.row.col.f32.f16.f16.f32 "
        "{%0,%1,%2,%3}, {%4,%5,%6,%7}, {%8,%9}, {%0,%1,%2,%3};"
        : "+f"(d[0]), "+f"(d[1]), "+f"(d[2]), "+f"(d[3])
        : "r"(a[0]), "r"(a[1]), "r"(a[2]), "r"(a[3]), "r"(b[0]), "r"(b[1]));
}

__device__ __forceinline__ float block_sum(float v) {
    __shared__ float sh[8];
    int lane = threadIdx.x & 31, w = threadIdx.x >> 5;
#pragma unroll
    for (int o = 16; o; o >>= 1) v += __shfl_xor_sync(0xffffffffu, v, o);
    if (lane == 0) sh[w] = v;
    __syncthreads();
    v = sh[0] + sh[1] + sh[2] + sh[3] + sh[4] + sh[5] + sh[6] + sh[7];
    __syncthreads();
    return v;
}
__device__ __forceinline__ float block_max(float v) {
    __shared__ float sh[8];
    int lane = threadIdx.x & 31, w = threadIdx.x >> 5;
#pragma unroll
    for (int o = 16; o; o >>= 1) v = fmaxf(v, __shfl_xor_sync(0xffffffffu, v, o));
    if (lane == 0) sh[w] = v;
    __syncthreads();
    v = fmaxf(fmaxf(fmaxf(sh[0], sh[1]), fmaxf(sh[2], sh[3])),
              fmaxf(fmaxf(sh[4], sh[5]), fmaxf(sh[6], sh[7])));
    __syncthreads();
    return v;
}

// ---------------- embedding / layernorm --------------------------------------
__global__ void embed_kernel(const int* __restrict__ ids,
                             const float* __restrict__ wte,
                             const float* __restrict__ wpe,
                             float* __restrict__ x) {
    int tok = blockIdx.x, t = tok & (NT - 1), id = ids[tok];
    const float* src = wte + (size_t)id * NC;
    const float* pp  = wpe + (size_t)t * NC;
    float* dst = x + (size_t)tok * NC;
    for (int c = threadIdx.x; c < NC; c += blockDim.x) dst[c] = src[c] + pp[c];
}

__global__ void __launch_bounds__(256) ln_kernel(const float* __restrict__ x,
                                                 const float* __restrict__ w,
                                                 const float* __restrict__ b,
                                                 float* __restrict__ o) {
    int row = blockIdx.x, tid = threadIdx.x;
    const float* xr = x + (size_t)row * NC;
    float v[4]; float s = 0.f;
#pragma unroll
    for (int i = 0; i < 4; i++) { v[i] = xr[tid + 256 * i]; s += v[i]; }
    s = block_sum(s);
    float mean = s * (1.f / NC), s2 = 0.f;
#pragma unroll
    for (int i = 0; i < 4; i++) { float d = v[i] - mean; s2 += d * d; }
    s2 = block_sum(s2);
    float rstd = rsqrtf(s2 * (1.f / NC) + 1e-5f);
    float* orow = o + (size_t)row * NC;
#pragma unroll
    for (int i = 0; i < 4; i++) {
        int c = tid + 256 * i;
        orow[c] = (v[i] - mean) * rstd * w[c] + b[c];
    }
}

// =============================================================================
// FP16 tensor-core GEMM (mma.sync m16n8k16, fp32 accum).
// 128x128 tile, KC=16 per stage, double-buffered smem with register prefetch.
// 256 threads = 8 warps (2x4), warp tile 64x32 = 4x4 m16n8 atoms.
// smem per stage: A frags 1024 u32 (4KB), B frags 1024 u32 (4KB).
// Fragment maps (m16n8k16, PTX ISA):
//   A(r,k): lane=(r&7)*4+((k>>1)&3), reg=(r>>3)+2*(k>>3), half=k&1
//   B(k,n): lane=(n&7)*4+((k>>1)&3), reg=k>>3,            half=k&1
// =============================================================================

template <int EPI>   // 0 store, 1 residual add, 2 exact GELU
__global__ void __launch_bounds__(256) hgemm_nn(const float* __restrict__ A,
                                                const float* __restrict__ B,
                                                const float* __restrict__ bias,
                                                float* __restrict__ D,
                                                int M, int N, int K) {
    __shared__ uint32_t smA[2][1024];
    __shared__ uint32_t smB[2][1024];

    const int tid  = threadIdx.x;
    const int lane = tid & 31;
    const int warp = tid >> 5;
    const int wm   = warp >> 2;   // 0..1
    const int wn   = warp & 3;    // 0..3
    const int bx = blockIdx.x, by = blockIdx.y;

    // A staging: thread -> row r=tid>>1, k-half kh=tid&1 (8 floats)
    const int ar  = tid >> 1;
    const int akh = tid & 1;
    const int art = ar & 15;
    // base for jj=0: idx = (ar>>4)*128 + ((art&7)*4 + jj)*4 + (art>>3) + 2*akh
    const int abase = (ar >> 4) * 128 + (art & 7) * 16 + (art >> 3) + 2 * akh;
    const float* Ag = A + (size_t)(by * 128 + ar) * K + akh * 8;

    // B staging: thread -> k rows 2kp,2kp+1 (kp=tid>>5), n0=(tid&31)*4 (4 cols)
    const int bkp = tid >> 5;
    const int bn0 = (tid & 31) * 4;
    // idx(n=n0+i) = (n>>3)*64 + ((n&7)*4 + (kp&3))*2 + (kp>>2)
    const float* Bg0 = B + (size_t)(2 * bkp)     * N + bx * 128 + bn0;
    const float* Bg1 = B + (size_t)(2 * bkp + 1) * N + bx * 128 + bn0;

    float acc[4][4][4];
#pragma unroll
    for (int i = 0; i < 4; i++)
#pragma unroll
        for (int j = 0; j < 4; j++)
#pragma unroll
            for (int r = 0; r < 4; r++) acc[i][j][r] = 0.f;

    const int KT = K >> 4;
    float4 pa0, pa1, pb0, pb1;

    // prologue
    pa0 = *reinterpret_cast<const float4*>(Ag);
    pa1 = *reinterpret_cast<const float4*>(Ag + 4);
    pb0 = *reinterpret_cast<const float4*>(Bg0);
    pb1 = *reinterpret_cast<const float4*>(Bg1);
    {
        float va[8] = {pa0.x, pa0.y, pa0.z, pa0.w, pa1.x, pa1.y, pa1.z, pa1.w};
        float v0[4] = {pb0.x, pb0.y, pb0.z, pb0.w};
        float v1[4] = {pb1.x, pb1.y, pb1.z, pb1.w};
#pragma unroll
        for (int jj = 0; jj < 4; jj++)
            smA[0][abase + jj * 4] = f2h2(va[2 * jj], va[2 * jj + 1]);
#pragma unroll
        for (int i = 0; i < 4; i++) {
            int n = bn0 + i;
            smB[0][(n >> 3) * 64 + ((n & 7) * 4 + (bkp & 3)) * 2 + (bkp >> 2)] =
                f2h2(v0[i], v1[i]);
        }
    }
    __syncthreads();

    for (int kt = 0; kt < KT; kt++) {
        const int s = kt & 1;
        if (kt + 1 < KT) {
            const float* Ap  = Ag  + (size_t)(kt + 1) * 16;
            const float* Bp0 = Bg0 + (size_t)(kt + 1) * 16 * N;
            const float* Bp1 = Bg1 + (size_t)(kt + 1) * 16 * N;
            pa0 = *reinterpret_cast<const float4*>(Ap);
            pa1 = *reinterpret_cast<const float4*>(Ap + 4);
            pb0 = *reinterpret_cast<const float4*>(Bp0);
            pb1 = *reinterpret_cast<const float4*>(Bp1);
        }
        // compute on stage s
        {
            uint32_t af[4][4], bf[4][2];
#pragma unroll
            for (int mt = 0; mt < 4; mt++)
                *reinterpret_cast<uint4*>(af[mt]) =
                    *reinterpret_cast<const uint4*>(&smA[s][(wm * 4 + mt) * 128 + lane * 4]);
#pragma unroll
            for (int nt = 0; nt < 4; nt++)
                *reinterpret_cast<uint2*>(bf[nt]) =
                    *reinterpret_cast<const uint2*>(&smB[s][(wn * 4 + nt) * 64 + lane * 2]);
#pragma unroll
            for (int mt = 0; mt < 4; mt++)
#pragma unroll
                for (int nt = 0; nt < 4; nt++)
                    mma_f16(acc[mt][nt], af[mt], bf[nt]);
        }
        if (kt + 1 < KT) {
            float va[8] = {pa0.x, pa0.y, pa0.z, pa0.w, pa1.x, pa1.y, pa1.z, pa1.w};
            float v0[4] = {pb0.x, pb0.y, pb0.z, pb0.w};
            float v1[4] = {pb1.x, pb1.y, pb1.z, pb1.w};
            const int ns = s ^ 1;
#pragma unroll
            for (int jj = 0; jj < 4; jj++)
                smA[ns][abase + jj * 4] = f2h2(va[2 * jj], va[2 * jj + 1]);
#pragma unroll
            for (int i = 0; i < 4; i++) {
                int n = bn0 + i;
                smB[ns][(n >> 3) * 64 + ((n & 7) * 4 + (bkp & 3)) * 2 + (bkp >> 2)] =
                    f2h2(v0[i], v1[i]);
            }
        }
        __syncthreads();
    }

    // epilogue
#pragma unroll
    for (int mt = 0; mt < 4; mt++) {
        const int row0 = by * 128 + wm * 64 + mt * 16 + (lane >> 2);
#pragma unroll
        for (int nt = 0; nt < 4; nt++) {
            const int col0 = bx * 128 + wn * 32 + nt * 8 + (lane & 3) * 2;
#pragma unroll
            for (int half = 0; half < 2; half++) {
                float* drow = D + (size_t)(row0 + half * 8) * N + col0;
                float v0 = acc[mt][nt][half * 2 + 0] + bias[col0];
                float v1 = acc[mt][nt][half * 2 + 1] + bias[col0 + 1];
                if (EPI == 1) { v0 += drow[0]; v1 += drow[1]; }
                if (EPI == 2) {
                    v0 = 0.5f * v0 * (1.f + erff(v0 * 0.70710678118654752f));
                    v1 = 0.5f * v1 * (1.f + erff(v1 * 0.70710678118654752f));
                }
                drow[0] = v0; drow[1] = v1;
            }
        }
    }
}

// NT variant: D = A[M,K] @ B[N,K]^T, ragged N (lm_head), no bias
__global__ void __launch_bounds__(256) hgemm_nt(const float* __restrict__ A,
                                                const float* __restrict__ B,
                                                float* __restrict__ D,
                                                int M, int N, int K) {
    __shared__ uint32_t smA[2][1024];
    __shared__ uint32_t smB[2][1024];

    const int tid  = threadIdx.x;
    const int lane = tid & 31;
    const int warp = tid >> 5;
    const int wm   = warp >> 2;
    const int wn   = warp & 3;
    const int bx = blockIdx.x, by = blockIdx.y;

    const int ar  = tid >> 1;
    const int akh = tid & 1;
    const int art = ar & 15;
    const int abase = (ar >> 4) * 128 + (art & 7) * 16 + (art >> 3) + 2 * akh;
    const float* Ag = A + (size_t)(by * 128 + ar) * K + akh * 8;

    // B: thread -> n row nr=tid>>1, k-half kh=tid&1 (8 k floats, contiguous)
    const int nr  = tid >> 1;
    const int gn  = bx * 128 + nr;
    const bool nok = (gn < N);
    const float* Bg = nok ? (B + (size_t)gn * K + akh * 8) : Ag;
    // idx(jj) = (nr>>3)*64 + ((nr&7)*4 + jj)*2 + kh
    const int bbase = (nr >> 3) * 64 + (nr & 7) * 8 + akh;

    float acc[4][4][4];
#pragma unroll
    for (int i = 0; i < 4; i++)
#pragma unroll
        for (int j = 0; j < 4; j++)
#pragma unroll
            for (int r = 0; r < 4; r++) acc[i][j][r] = 0.f;

    const int KT = K >> 4;
    float4 pa0, pa1, pb0, pb1;

    pa0 = *reinterpret_cast<const float4*>(Ag);
    pa1 = *reinterpret_cast<const float4*>(Ag + 4);
    pb0 = *reinterpret_cast<const float4*>(Bg);
    pb1 = *reinterpret_cast<const float4*>(Bg + 4);
    if (!nok) { pb0 = make_float4(0, 0, 0, 0); pb1 = pb0; }
    {
        float va[8] = {pa0.x, pa0.y, pa0.z, pa0.w, pa1.x, pa1.y, pa1.z, pa1.w};
        float vb[8] = {pb0.x, pb0.y, pb0.z, pb0.w, pb1.x, pb1.y, pb1.z, pb1.w};
#pragma unroll
        for (int jj = 0; jj < 4; jj++) {
            smA[0][abase + jj * 4] = f2h2(va[2 * jj], va[2 * jj + 1]);
            smB[0][bbase + jj * 2] = f2h2(vb[2 * jj], vb[2 * jj + 1]);
        }
    }
    __syncthreads();

    for (int kt = 0; kt < KT; kt++) {
        const int s = kt & 1;
        if (kt + 1 < KT) {
            const float* Ap = Ag + (size_t)(kt + 1) * 16;
            const float* Bp = Bg + (size_t)(kt + 1) * 16;
            pa0 = *reinterpret_cast<const float4*>(Ap);
            pa1 = *reinterpret_cast<const float4*>(Ap + 4);
            pb0 = *reinterpret_cast<const float4*>(Bp);
            pb1 = *reinterpret_cast<const float4*>(Bp + 4);
            if (!nok) { pb0 = make_float4(0, 0, 0, 0); pb1 = pb0; }
        }
        {
            uint32_t af[4][4], bf[4][2];
#pragma unroll
            for (int mt = 0; mt < 4; mt++)
                *reinterpret_cast<uint4*>(af[mt]) =
                    *reinterpret_cast<const uint4*>(&smA[s][(wm * 4 + mt) * 128 + lane * 4]);
#pragma unroll
            for (int nt = 0; nt < 4; nt++)
                *reinterpret_cast<uint2*>(bf[nt]) =
                    *reinterpret_cast<const uint2*>(&smB[s][(wn * 4 + nt) * 64 + lane * 2]);
#pragma unroll
            for (int mt = 0; mt < 4; mt++)
#pragma unroll
                for (int nt = 0; nt < 4; nt++)
                    mma_f16(acc[mt][nt], af[mt], bf[nt]);
        }
        if (kt + 1 < KT) {
            float va[8] = {pa0.x, pa0.y, pa0.z, pa0.w, pa1.x, pa1.y, pa1.z, pa1.w};
            float vb[8] = {pb0.x, pb0.y, pb0.z, pb0.w, pb1.x, pb1.y, pb1.z, pb1.w};
            const int ns = s ^ 1;
#pragma unroll
            for (int jj = 0; jj < 4; jj++) {
                smA[ns][abase + jj * 4] = f2h2(va[2 * jj], va[2 * jj + 1]);
                smB[ns][bbase + jj * 2] = f2h2(vb[2 * jj], vb[2 * jj + 1]);
            }
        }
        __syncthreads();
    }

#pragma unroll
    for (int mt = 0; mt < 4; mt++) {
        const int row0 = by * 128 + wm * 64 + mt * 16 + (lane >> 2);
#pragma unroll
        for (int nt = 0; nt < 4; nt++) {
            const int col0 = bx * 128 + wn * 32 + nt * 8 + (lane & 3) * 2;
#pragma unroll
            for (int half = 0; half < 2; half++) {
                float* drow = D + (size_t)(row0 + half * 8) * N;
                if (col0 < N)     drow[col0]     = acc[mt][nt][half * 2 + 0];
                if (col0 + 1 < N) drow[col0 + 1] = acc[mt][nt][half * 2 + 1];
            }
        }
    }
}

// ---------------- attention (fp32, unchanged) --------------------------------
__global__ void __launch_bounds__(256) attn_scores(const float* __restrict__ qkv,
                                                   float* __restrict__ att) {
    const int bh = blockIdx.z, b = bh >> 4, h = bh & 15;
    const int qt = blockIdx.y, kt = blockIdx.x;
    __shared__ float Qs[64][65];
    __shared__ float Ks[64][65];
    const int tid = threadIdx.x;
    const int lrow = tid >> 2, d0 = (tid & 3) << 4;
    const float* qp = qkv + (size_t)(b * NT + qt * 64 + lrow) * C3 + h * NHD + d0;
    const float* kp = qkv + (size_t)(b * NT + kt * 64 + lrow) * C3 + NC + h * NHD + d0;
#pragma unroll
    for (int i = 0; i < 4; i++) {
        float4 qv = *reinterpret_cast<const float4*>(qp + 4 * i);
        float4 kv = *reinterpret_cast<const float4*>(kp + 4 * i);
        Qs[lrow][d0 + 4 * i + 0] = qv.x; Qs[lrow][d0 + 4 * i + 1] = qv.y;
        Qs[lrow][d0 + 4 * i + 2] = qv.z; Qs[lrow][d0 + 4 * i + 3] = qv.w;
        Ks[lrow][d0 + 4 * i + 0] = kv.x; Ks[lrow][d0 + 4 * i + 1] = kv.y;
        Ks[lrow][d0 + 4 * i + 2] = kv.z; Ks[lrow][d0 + 4 * i + 3] = kv.w;
    }
    __syncthreads();
    const int tr = tid >> 4, tc = tid & 15;
    float acc[4][4] = {};
#pragma unroll
    for (int d = 0; d < 64; d++) {
        float ar[4], br[4];
#pragma unroll
        for (int i = 0; i < 4; i++) ar[i] = Qs[tr * 4 + i][d];
#pragma unroll
        for (int j = 0; j < 4; j++) br[j] = Ks[tc * 4 + j][d];
#pragma unroll
        for (int i = 0; i < 4; i++)
#pragma unroll
            for (int j = 0; j < 4; j++) acc[i][j] += ar[i] * br[j];
    }
#pragma unroll
    for (int i = 0; i < 4; i++) {
        float* dst = att + ((size_t)bh * NT + qt * 64 + tr * 4 + i) * NT + kt * 64 + tc * 4;
#pragma unroll
        for (int j = 0; j < 4; j++) dst[j] = acc[i][j] * 0.125f;
    }
}

__global__ void __launch_bounds__(256) softmax_kernel(float* __restrict__ att) {
    float* p = att + (size_t)blockIdx.x * NT;
    int tid = threadIdx.x;
    float v[4]; float m = -1e30f;
#pragma unroll
    for (int i = 0; i < 4; i++) { v[i] = p[tid + 256 * i]; m = fmaxf(m, v[i]); }
    m = block_max(m);
    float s = 0.f;
#pragma unroll
    for (int i = 0; i < 4; i++) { v[i] = __expf(v[i] - m); s += v[i]; }
    s = block_sum(s);
    float inv = 1.f / s;
#pragma unroll
    for (int i = 0; i < 4; i++) p[tid + 256 * i] = v[i] * inv;
}

__global__ void __launch_bounds__(256) attn_av(const float* __restrict__ att,
                                               const float* __restrict__ qkv,
                                               float* __restrict__ y) {
    const int bh = blockIdx.y, b = bh >> 4, h = bh & 15;
    const int qt = blockIdx.x;
    __shared__ float Ps[64][68];
    __shared__ float Vs[64][68];
    const int tid = threadIdx.x;
    const int lrow = tid >> 2, c0 = (tid & 3) << 4;
    const int tr = tid >> 4, tc = tid & 15;
    float acc[4][4] = {};
    for (int kt = 0; kt < 16; kt++) {
        const float* pp = att + ((size_t)bh * NT + qt * 64 + lrow) * NT + kt * 64 + c0;
        const float* vp = qkv + (size_t)(b * NT + kt * 64 + lrow) * C3 + 2 * NC + h * NHD + c0;
#pragma unroll
        for (int i = 0; i < 4; i++) {
            float4 pv = *reinterpret_cast<const float4*>(pp + 4 * i);
            float4 vv = *reinterpret_cast<const float4*>(vp + 4 * i);
            Ps[lrow][c0 + 4 * i + 0] = pv.x; Ps[lrow][c0 + 4 * i + 1] = pv.y;
            Ps[lrow][c0 + 4 * i + 2] = pv.z; Ps[lrow][c0 + 4 * i + 3] = pv.w;
            Vs[lrow][c0 + 4 * i + 0] = vv.x; Vs[lrow][c0 + 4 * i + 1] = vv.y;
            Vs[lrow][c0 + 4 * i + 2] = vv.z; Vs[lrow][c0 + 4 * i + 3] = vv.w;
        }
        __syncthreads();
#pragma unroll
        for (int kk = 0; kk < 64; kk++) {
            float ar[4], br[4];
#pragma unroll
            for (int i = 0; i < 4; i++) ar[i] = Ps[tr * 4 + i][kk];
            float4 bv = *reinterpret_cast<const float4*>(&Vs[kk][tc * 4]);
            br[0] = bv.x; br[1] = bv.y; br[2] = bv.z; br[3] = bv.w;
#pragma unroll
            for (int i = 0; i < 4; i++)
#pragma unroll
                for (int j = 0; j < 4; j++) acc[i][j] += ar[i] * br[j];
        }
        __syncthreads();
    }
#pragma unroll
    for (int i = 0; i < 4; i++) {
        float* dst = y + (size_t)(b * NT + qt * 64 + tr * 4 + i) * NC + h * NHD + tc * 4;
#pragma unroll
        for (int j = 0; j < 4; j++) dst[j] = acc[i][j];
    }
}

// ---------------- host orchestration -----------------------------------------
extern "C" void kernel_launch(void* const* d_in, const int* in_sizes, int n_in,
                              void* d_out, int out_size) {
    const int*   ids    = (const int*)  d_in[0];
    const float* wte    = (const float*)d_in[1];
    const float* wpe    = (const float*)d_in[2];
    const float* ln1_w  = (const float*)d_in[3];
    const float* ln1_b  = (const float*)d_in[4];
    const float* attn_w = (const float*)d_in[5];
    const float* attn_b = (const float*)d_in[6];
    const float* proj_w = (const float*)d_in[7];
    const float* proj_b = (const float*)d_in[8];
    const float* ln2_w  = (const float*)d_in[9];
    const float* ln2_b  = (const float*)d_in[10];
    const float* fc_w   = (const float*)d_in[11];
    const float* fc_b   = (const float*)d_in[12];
    const float* fc2_w  = (const float*)d_in[13];
    const float* fc2_b  = (const float*)d_in[14];
    const float* lnf_w  = (const float*)d_in[15];
    const float* lnf_b  = (const float*)d_in[16];
    float* out = (float*)d_out;

    float *x, *h, *qkv, *att, *y, *mlp;
    cudaGetSymbolAddress((void**)&x,   g_x);
    cudaGetSymbolAddress((void**)&h,   g_h);
    cudaGetSymbolAddress((void**)&qkv, g_qkv);
    cudaGetSymbolAddress((void**)&att, g_att);
    cudaGetSymbolAddress((void**)&y,   g_y);
    cudaGetSymbolAddress((void**)&mlp, g_mlp);

    embed_kernel<<<NTOK, 256>>>(ids, wte, wpe, x);

    for (int l = 0; l < NL; l++) {
        ln_kernel<<<NTOK, 256>>>(x, ln1_w + (size_t)l * NC, ln1_b + (size_t)l * NC, h);
        hgemm_nn<0><<<dim3(C3 / 128, NTOK / 128), 256>>>(
            h, attn_w + (size_t)l * NC * C3, attn_b + (size_t)l * C3, qkv, NTOK, C3, NC);
        attn_scores<<<dim3(NT / 64, NT / 64, NB * NH), 256>>>(qkv, att);
        softmax_kernel<<<NB * NH * NT, 256>>>(att);
        attn_av<<<dim3(NT / 64, NB * NH), 256>>>(att, qkv, y);
        hgemm_nn<1><<<dim3(NC / 128, NTOK / 128), 256>>>(
            y, proj_w + (size_t)l * NC * NC, proj_b + (size_t)l * NC, x, NTOK, NC, NC);
        ln_kernel<<<NTOK, 256>>>(x, ln2_w + (size_t)l * NC, ln2_b + (size_t)l * NC, h);
        hgemm_nn<2><<<dim3(C4 / 128, NTOK / 128), 256>>>(
            h, fc_w + (size_t)l * NC * C4, fc_b + (size_t)l * C4, mlp, NTOK, C4, NC);
        hgemm_nn<1><<<dim3(NC / 128, NTOK / 128), 256>>>(
            mlp, fc2_w + (size_t)l * C4 * NC, fc2_b + (size_t)l * NC, x, NTOK, NC, C4);
    }

    ln_kernel<<<NTOK, 256>>>(x, lnf_w, lnf_b, h);
    hgemm_nt<<<dim3((NV + 127) / 128, NTOK / 128), 256>>>(h, wte, out, NTOK, NV, NC);
}

// round 6
// speedup vs baseline: 2.0170x; 1.0355x over previous
#include <cuda_runtime.h>
#include <cuda_fp16.h>
#include <math.h>
#include <stdint.h>

// Problem dims
#define NL   8
#define NB   2
#define NT   1024
#define NC   1024
#define NH   16
#define NHD  64
#define NV   50257
#define NTOK 2048
#define C3   3072
#define C4   4096

// ---------------- scratch ----------------------------------------------------
__device__ float  g_x  [NTOK * NC];                 // residual (fp32)
__device__ float  g_qkv[NTOK * C3];                 // qkv (fp32, attention input)
__device__ float  g_att[(size_t)NB * NH * NT * NT]; // attention scores
__device__ __half g_h16 [NTOK * NC];                // LN output (GEMM A)
__device__ __half g_y16 [NTOK * NC];                // attn output (GEMM A)
__device__ __half g_mlp16[NTOK * C4];               // GELU output (GEMM A)
// fp16 weights (converted once per launch)
__device__ __half w16_attn[(size_t)NL * NC * C3];
__device__ __half w16_proj[(size_t)NL * NC * NC];
__device__ __half w16_fc  [(size_t)NL * NC * C4];
__device__ __half w16_fc2 [(size_t)NL * C4 * NC];
__device__ __half w16_wte [(size_t)NV * NC];

// ---------------- helpers ----------------------------------------------------
__device__ __forceinline__ void mma_f16(float* d, const uint32_t* a, const uint32_t* b) {
    asm volatile(
        "mma.sync.aligned.m16n8k16.row.col.f32.f16.f16.f32 "
        "{%0,%1,%2,%3}, {%4,%5,%6,%7}, {%8,%9}, {%0,%1,%2,%3};"
        : "+f"(d[0]), "+f"(d[1]), "+f"(d[2]), "+f"(d[3])
        : "r"(a[0]), "r"(a[1]), "r"(a[2]), "r"(a[3]), "r"(b[0]), "r"(b[1]));
}

__device__ __forceinline__ float block_sum(float v) {
    __shared__ float sh[8];
    int lane = threadIdx.x & 31, w = threadIdx.x >> 5;
#pragma unroll
    for (int o = 16; o; o >>= 1) v += __shfl_xor_sync(0xffffffffu, v, o);
    if (lane == 0) sh[w] = v;
    __syncthreads();
    v = sh[0] + sh[1] + sh[2] + sh[3] + sh[4] + sh[5] + sh[6] + sh[7];
    __syncthreads();
    return v;
}
__device__ __forceinline__ float block_max(float v) {
    __shared__ float sh[8];
    int lane = threadIdx.x & 31, w = threadIdx.x >> 5;
#pragma unroll
    for (int o = 16; o; o >>= 1) v = fmaxf(v, __shfl_xor_sync(0xffffffffu, v, o));
    if (lane == 0) sh[w] = v;
    __syncthreads();
    v = fmaxf(fmaxf(fmaxf(sh[0], sh[1]), fmaxf(sh[2], sh[3])),
              fmaxf(fmaxf(sh[4], sh[5]), fmaxf(sh[6], sh[7])));
    __syncthreads();
    return v;
}

// ---------------- weight conversion (runs once per launch) -------------------
__global__ void __launch_bounds__(256) cvt_f2h(const float* __restrict__ in,
                                               __half* __restrict__ out, int n4) {
    int i = blockIdx.x * 256 + threadIdx.x;
    if (i < n4) {
        float4 v = reinterpret_cast<const float4*>(in)[i];
        __half2* o = reinterpret_cast<__half2*>(out) + 2 * (size_t)i;
        o[0] = __floats2half2_rn(v.x, v.y);
        o[1] = __floats2half2_rn(v.z, v.w);
    }
}

// ---------------- embedding / layernorm --------------------------------------
__global__ void embed_kernel(const int* __restrict__ ids,
                             const float* __restrict__ wte,
                             const float* __restrict__ wpe,
                             float* __restrict__ x) {
    int tok = blockIdx.x, t = tok & (NT - 1), id = ids[tok];
    const float* src = wte + (size_t)id * NC;
    const float* pp  = wpe + (size_t)t * NC;
    float* dst = x + (size_t)tok * NC;
    for (int c = threadIdx.x; c < NC; c += blockDim.x) dst[c] = src[c] + pp[c];
}

// layernorm -> fp16 output (feeds GEMM A operand)
__global__ void __launch_bounds__(256) ln_kernel(const float* __restrict__ x,
                                                 const float* __restrict__ w,
                                                 const float* __restrict__ b,
                                                 __half* __restrict__ o) {
    int row = blockIdx.x, tid = threadIdx.x;
    const float* xr = x + (size_t)row * NC;
    float v[4]; float s = 0.f;
#pragma unroll
    for (int i = 0; i < 4; i++) { v[i] = xr[tid + 256 * i]; s += v[i]; }
    s = block_sum(s);
    float mean = s * (1.f / NC), s2 = 0.f;
#pragma unroll
    for (int i = 0; i < 4; i++) { float d = v[i] - mean; s2 += d * d; }
    s2 = block_sum(s2);
    float rstd = rsqrtf(s2 * (1.f / NC) + 1e-5f);
    __half* orow = o + (size_t)row * NC;
#pragma unroll
    for (int i = 0; i < 4; i++) {
        int c = tid + 256 * i;
        orow[c] = __float2half((v[i] - mean) * rstd * w[c] + b[c]);
    }
}

// =============================================================================
// FP16 GEMM (mma.sync m16n8k16, fp32 accum), fp16 operands in global.
// 128x128 tile, KC=32 (2 k-steps per stage), double-buffered fragment smem.
// 256 threads = 8 warps (2x4), warp tile 64x32.
// Fragment maps (m16n8k16): A(r,k): idx=(r>>4)*128+(r&7)*16+((r>>3)&1)
//    + (jj&3)*4 + (jj>>2)*2  where jj=k>>1.   B(k,n): idx=(n>>3)*64
//    + ((n&7)*4+(jj&3))*2 + (jj>>2).  Each kstep block = 1024 u32.
// =============================================================================

// EPI: 0 store fp32   1 residual add fp32   2 exact GELU -> fp16
template <int EPI>
__global__ void __launch_bounds__(256) hgemm_nn(const __half* __restrict__ A,
                                                const __half* __restrict__ B,
                                                const float* __restrict__ bias,
                                                void* __restrict__ Dv,
                                                int M, int N, int K) {
    __shared__ uint32_t smA[2][2048];
    __shared__ uint32_t smB[2][2048];

    const int tid  = threadIdx.x;
    const int lane = tid & 31;
    const int warp = tid >> 5;
    const int wm   = warp >> 2;
    const int wn   = warp & 3;
    const int bx = blockIdx.x, by = blockIdx.y;

    // A staging: row ar=tid>>1, kstep s2=tid&1 (16 halves = 2 uint4)
    const int ar = tid >> 1;
    const int as2 = tid & 1;
    const int abase = as2 * 1024 + (ar >> 4) * 128 + (ar & 7) * 16 + ((ar >> 3) & 1);
    const __half* Ag = A + (size_t)(by * 128 + ar) * K + as2 * 16;

    // B staging: kp=tid>>5 (pair row in each kstep), n0=(tid&31)*4
    const int bkp = tid >> 5;
    const int bn0 = (tid & 31) * 4;
    const __half* Bg = B + bx * 128 + bn0;
    // store bases per kstep: (n>>3)*64 + ((n&7)*4+(kp&3))*2 + (kp>>2)
    int bst[4];
#pragma unroll
    for (int i = 0; i < 4; i++) {
        int n = bn0 + i;
        bst[i] = (n >> 3) * 64 + ((n & 7) * 4 + (bkp & 3)) * 2 + (bkp >> 2);
    }

    float acc[4][4][4];
#pragma unroll
    for (int i = 0; i < 4; i++)
#pragma unroll
        for (int j = 0; j < 4; j++)
#pragma unroll
            for (int r = 0; r < 4; r++) acc[i][j][r] = 0.f;

    const int KT = K >> 5;
    uint4 pa0, pa1;
    uint2 pb[2][2];   // [kstep][row parity]

    // prologue: load tile 0
    pa0 = *reinterpret_cast<const uint4*>(Ag);
    pa1 = *reinterpret_cast<const uint4*>(Ag + 8);
#pragma unroll
    for (int s2 = 0; s2 < 2; s2++) {
        pb[s2][0] = *reinterpret_cast<const uint2*>(Bg + (size_t)(s2 * 16 + 2 * bkp) * N);
        pb[s2][1] = *reinterpret_cast<const uint2*>(Bg + (size_t)(s2 * 16 + 2 * bkp + 1) * N);
    }
    {
        const uint32_t* aw = reinterpret_cast<const uint32_t*>(&pa0);
#pragma unroll
        for (int jj = 0; jj < 4; jj++) smA[0][abase + jj * 4] = aw[jj];
        aw = reinterpret_cast<const uint32_t*>(&pa1);
#pragma unroll
        for (int jj = 0; jj < 4; jj++) smA[0][abase + jj * 4 + 2] = aw[jj];
#pragma unroll
        for (int s2 = 0; s2 < 2; s2++) {
            uint32_t w0 = __byte_perm(pb[s2][0].x, pb[s2][1].x, 0x5410);
            uint32_t w1 = __byte_perm(pb[s2][0].x, pb[s2][1].x, 0x7632);
            uint32_t w2 = __byte_perm(pb[s2][0].y, pb[s2][1].y, 0x5410);
            uint32_t w3 = __byte_perm(pb[s2][0].y, pb[s2][1].y, 0x7632);
            smB[0][s2 * 1024 + bst[0]] = w0;
            smB[0][s2 * 1024 + bst[1]] = w1;
            smB[0][s2 * 1024 + bst[2]] = w2;
            smB[0][s2 * 1024 + bst[3]] = w3;
        }
    }
    __syncthreads();

    for (int kt = 0; kt < KT; kt++) {
        const int s = kt & 1;
        if (kt + 1 < KT) {
            const __half* Ap = Ag + (size_t)(kt + 1) * 32;
            pa0 = *reinterpret_cast<const uint4*>(Ap);
            pa1 = *reinterpret_cast<const uint4*>(Ap + 8);
            const __half* Bp = Bg + (size_t)(kt + 1) * 32 * N;
#pragma unroll
            for (int s2 = 0; s2 < 2; s2++) {
                pb[s2][0] = *reinterpret_cast<const uint2*>(Bp + (size_t)(s2 * 16 + 2 * bkp) * N);
                pb[s2][1] = *reinterpret_cast<const uint2*>(Bp + (size_t)(s2 * 16 + 2 * bkp + 1) * N);
            }
        }
        // compute both ksteps of stage s
#pragma unroll
        for (int s2 = 0; s2 < 2; s2++) {
            uint32_t af[4][4], bf[4][2];
#pragma unroll
            for (int mt = 0; mt < 4; mt++)
                *reinterpret_cast<uint4*>(af[mt]) =
                    *reinterpret_cast<const uint4*>(&smA[s][s2 * 1024 + (wm * 4 + mt) * 128 + lane * 4]);
#pragma unroll
            for (int nt = 0; nt < 4; nt++)
                *reinterpret_cast<uint2*>(bf[nt]) =
                    *reinterpret_cast<const uint2*>(&smB[s][s2 * 1024 + (wn * 4 + nt) * 64 + lane * 2]);
#pragma unroll
            for (int mt = 0; mt < 4; mt++)
#pragma unroll
                for (int nt = 0; nt < 4; nt++)
                    mma_f16(acc[mt][nt], af[mt], bf[nt]);
        }
        if (kt + 1 < KT) {
            const int ns = s ^ 1;
            const uint32_t* aw = reinterpret_cast<const uint32_t*>(&pa0);
#pragma unroll
            for (int jj = 0; jj < 4; jj++) smA[ns][abase + jj * 4] = aw[jj];
            aw = reinterpret_cast<const uint32_t*>(&pa1);
#pragma unroll
            for (int jj = 0; jj < 4; jj++) smA[ns][abase + jj * 4 + 2] = aw[jj];
#pragma unroll
            for (int s2 = 0; s2 < 2; s2++) {
                uint32_t w0 = __byte_perm(pb[s2][0].x, pb[s2][1].x, 0x5410);
                uint32_t w1 = __byte_perm(pb[s2][0].x, pb[s2][1].x, 0x7632);
                uint32_t w2 = __byte_perm(pb[s2][0].y, pb[s2][1].y, 0x5410);
                uint32_t w3 = __byte_perm(pb[s2][0].y, pb[s2][1].y, 0x7632);
                smB[ns][s2 * 1024 + bst[0]] = w0;
                smB[ns][s2 * 1024 + bst[1]] = w1;
                smB[ns][s2 * 1024 + bst[2]] = w2;
                smB[ns][s2 * 1024 + bst[3]] = w3;
            }
        }
        __syncthreads();
    }

    // epilogue
#pragma unroll
    for (int mt = 0; mt < 4; mt++) {
        const int row0 = by * 128 + wm * 64 + mt * 16 + (lane >> 2);
#pragma unroll
        for (int nt = 0; nt < 4; nt++) {
            const int col0 = bx * 128 + wn * 32 + nt * 8 + (lane & 3) * 2;
#pragma unroll
            for (int half = 0; half < 2; half++) {
                float v0 = acc[mt][nt][half * 2 + 0] + bias[col0];
                float v1 = acc[mt][nt][half * 2 + 1] + bias[col0 + 1];
                if (EPI == 2) {
                    v0 = 0.5f * v0 * (1.f + erff(v0 * 0.70710678118654752f));
                    v1 = 0.5f * v1 * (1.f + erff(v1 * 0.70710678118654752f));
                    __half* drow = (__half*)Dv + (size_t)(row0 + half * 8) * N + col0;
                    *reinterpret_cast<__half2*>(drow) = __floats2half2_rn(v0, v1);
                } else {
                    float* drow = (float*)Dv + (size_t)(row0 + half * 8) * N + col0;
                    if (EPI == 1) { v0 += drow[0]; v1 += drow[1]; }
                    drow[0] = v0; drow[1] = v1;
                }
            }
        }
    }
}

// NT variant: D = A[M,K] @ B[N,K]^T (lm_head), fp16 operands, fp32 out
__global__ void __launch_bounds__(256) hgemm_nt(const __half* __restrict__ A,
                                                const __half* __restrict__ B,
                                                float* __restrict__ D,
                                                int M, int N, int K) {
    __shared__ uint32_t smA[2][2048];
    __shared__ uint32_t smB[2][2048];

    const int tid  = threadIdx.x;
    const int lane = tid & 31;
    const int warp = tid >> 5;
    const int wm   = warp >> 2;
    const int wn   = warp & 3;
    const int bx = blockIdx.x, by = blockIdx.y;

    const int ar = tid >> 1;
    const int as2 = tid & 1;
    const int abase = as2 * 1024 + (ar >> 4) * 128 + (ar & 7) * 16 + ((ar >> 3) & 1);
    const __half* Ag = A + (size_t)(by * 128 + ar) * K + as2 * 16;

    // B: n-row nr=tid>>1, same kstep split; k-contig like A
    const int nr = tid >> 1;
    const int gn = bx * 128 + nr;
    const bool nok = (gn < N);
    const __half* Bg = nok ? (B + (size_t)gn * K + as2 * 16) : Ag;
    const int bbase = as2 * 1024 + (nr >> 3) * 64 + (nr & 7) * 8;

    float acc[4][4][4];
#pragma unroll
    for (int i = 0; i < 4; i++)
#pragma unroll
        for (int j = 0; j < 4; j++)
#pragma unroll
            for (int r = 0; r < 4; r++) acc[i][j][r] = 0.f;

    const int KT = K >> 5;
    uint4 pa0, pa1, pb0, pb1;

    pa0 = *reinterpret_cast<const uint4*>(Ag);
    pa1 = *reinterpret_cast<const uint4*>(Ag + 8);
    pb0 = *reinterpret_cast<const uint4*>(Bg);
    pb1 = *reinterpret_cast<const uint4*>(Bg + 8);
    if (!nok) { pb0 = make_uint4(0, 0, 0, 0); pb1 = pb0; }
    {
        const uint32_t* aw = reinterpret_cast<const uint32_t*>(&pa0);
        const uint32_t* bw = reinterpret_cast<const uint32_t*>(&pb0);
#pragma unroll
        for (int jj = 0; jj < 4; jj++) {
            smA[0][abase + jj * 4] = aw[jj];
            smB[0][bbase + jj * 2] = bw[jj];
        }
        aw = reinterpret_cast<const uint32_t*>(&pa1);
        bw = reinterpret_cast<const uint32_t*>(&pb1);
#pragma unroll
        for (int jj = 0; jj < 4; jj++) {
            smA[0][abase + jj * 4 + 2] = aw[jj];
            smB[0][bbase + jj * 2 + 1] = bw[jj];
        }
    }
    __syncthreads();

    for (int kt = 0; kt < KT; kt++) {
        const int s = kt & 1;
        if (kt + 1 < KT) {
            const __half* Ap = Ag + (size_t)(kt + 1) * 32;
            const __half* Bp = Bg + (size_t)(kt + 1) * 32;
            pa0 = *reinterpret_cast<const uint4*>(Ap);
            pa1 = *reinterpret_cast<const uint4*>(Ap + 8);
            pb0 = *reinterpret_cast<const uint4*>(Bp);
            pb1 = *reinterpret_cast<const uint4*>(Bp + 8);
            if (!nok) { pb0 = make_uint4(0, 0, 0, 0); pb1 = pb0; }
        }
#pragma unroll
        for (int s2 = 0; s2 < 2; s2++) {
            uint32_t af[4][4], bf[4][2];
#pragma unroll
            for (int mt = 0; mt < 4; mt++)
                *reinterpret_cast<uint4*>(af[mt]) =
                    *reinterpret_cast<const uint4*>(&smA[s][s2 * 1024 + (wm * 4 + mt) * 128 + lane * 4]);
#pragma unroll
            for (int nt = 0; nt < 4; nt++)
                *reinterpret_cast<uint2*>(bf[nt]) =
                    *reinterpret_cast<const uint2*>(&smB[s][s2 * 1024 + (wn * 4 + nt) * 64 + lane * 2]);
#pragma unroll
            for (int mt = 0; mt < 4; mt++)
#pragma unroll
                for (int nt = 0; nt < 4; nt++)
                    mma_f16(acc[mt][nt], af[mt], bf[nt]);
        }
        if (kt + 1 < KT) {
            const int ns = s ^ 1;
            const uint32_t* aw = reinterpret_cast<const uint32_t*>(&pa0);
            const uint32_t* bw = reinterpret_cast<const uint32_t*>(&pb0);
#pragma unroll
            for (int jj = 0; jj < 4; jj++) {
                smA[ns][abase + jj * 4] = aw[jj];
                smB[ns][bbase + jj * 2] = bw[jj];
            }
            aw = reinterpret_cast<const uint32_t*>(&pa1);
            bw = reinterpret_cast<const uint32_t*>(&pb1);
#pragma unroll
            for (int jj = 0; jj < 4; jj++) {
                smA[ns][abase + jj * 4 + 2] = aw[jj];
                smB[ns][bbase + jj * 2 + 1] = bw[jj];
            }
        }
        __syncthreads();
    }

#pragma unroll
    for (int mt = 0; mt < 4; mt++) {
        const int row0 = by * 128 + wm * 64 + mt * 16 + (lane >> 2);
#pragma unroll
        for (int nt = 0; nt < 4; nt++) {
            const int col0 = bx * 128 + wn * 32 + nt * 8 + (lane & 3) * 2;
#pragma unroll
            for (int half = 0; half < 2; half++) {
                float* drow = D + (size_t)(row0 + half * 8) * N;
                if (col0 < N)     drow[col0]     = acc[mt][nt][half * 2 + 0];
                if (col0 + 1 < N) drow[col0 + 1] = acc[mt][nt][half * 2 + 1];
            }
        }
    }
}

// ---------------- attention (fp32, unchanged except y -> fp16) ---------------
__global__ void __launch_bounds__(256) attn_scores(const float* __restrict__ qkv,
                                                   float* __restrict__ att) {
    const int bh = blockIdx.z, b = bh >> 4, h = bh & 15;
    const int qt = blockIdx.y, kt = blockIdx.x;
    __shared__ float Qs[64][65];
    __shared__ float Ks[64][65];
    const int tid = threadIdx.x;
    const int lrow = tid >> 2, d0 = (tid & 3) << 4;
    const float* qp = qkv + (size_t)(b * NT + qt * 64 + lrow) * C3 + h * NHD + d0;
    const float* kp = qkv + (size_t)(b * NT + kt * 64 + lrow) * C3 + NC + h * NHD + d0;
#pragma unroll
    for (int i = 0; i < 4; i++) {
        float4 qv = *reinterpret_cast<const float4*>(qp + 4 * i);
        float4 kv = *reinterpret_cast<const float4*>(kp + 4 * i);
        Qs[lrow][d0 + 4 * i + 0] = qv.x; Qs[lrow][d0 + 4 * i + 1] = qv.y;
        Qs[lrow][d0 + 4 * i + 2] = qv.z; Qs[lrow][d0 + 4 * i + 3] = qv.w;
        Ks[lrow][d0 + 4 * i + 0] = kv.x; Ks[lrow][d0 + 4 * i + 1] = kv.y;
        Ks[lrow][d0 + 4 * i + 2] = kv.z; Ks[lrow][d0 + 4 * i + 3] = kv.w;
    }
    __syncthreads();
    const int tr = tid >> 4, tc = tid & 15;
    float acc[4][4] = {};
#pragma unroll
    for (int d = 0; d < 64; d++) {
        float ar[4], br[4];
#pragma unroll
        for (int i = 0; i < 4; i++) ar[i] = Qs[tr * 4 + i][d];
#pragma unroll
        for (int j = 0; j < 4; j++) br[j] = Ks[tc * 4 + j][d];
#pragma unroll
        for (int i = 0; i < 4; i++)
#pragma unroll
            for (int j = 0; j < 4; j++) acc[i][j] += ar[i] * br[j];
    }
#pragma unroll
    for (int i = 0; i < 4; i++) {
        float* dst = att + ((size_t)bh * NT + qt * 64 + tr * 4 + i) * NT + kt * 64 + tc * 4;
#pragma unroll
        for (int j = 0; j < 4; j++) dst[j] = acc[i][j] * 0.125f;
    }
}

__global__ void __launch_bounds__(256) softmax_kernel(float* __restrict__ att) {
    float* p = att + (size_t)blockIdx.x * NT;
    int tid = threadIdx.x;
    float v[4]; float m = -1e30f;
#pragma unroll
    for (int i = 0; i < 4; i++) { v[i] = p[tid + 256 * i]; m = fmaxf(m, v[i]); }
    m = block_max(m);
    float s = 0.f;
#pragma unroll
    for (int i = 0; i < 4; i++) { v[i] = __expf(v[i] - m); s += v[i]; }
    s = block_sum(s);
    float inv = 1.f / s;
#pragma unroll
    for (int i = 0; i < 4; i++) p[tid + 256 * i] = v[i] * inv;
}

__global__ void __launch_bounds__(256) attn_av(const float* __restrict__ att,
                                               const float* __restrict__ qkv,
                                               __half* __restrict__ y) {
    const int bh = blockIdx.y, b = bh >> 4, h = bh & 15;
    const int qt = blockIdx.x;
    __shared__ float Ps[64][68];
    __shared__ float Vs[64][68];
    const int tid = threadIdx.x;
    const int lrow = tid >> 2, c0 = (tid & 3) << 4;
    const int tr = tid >> 4, tc = tid & 15;
    float acc[4][4] = {};
    for (int kt = 0; kt < 16; kt++) {
        const float* pp = att + ((size_t)bh * NT + qt * 64 + lrow) * NT + kt * 64 + c0;
        const float* vp = qkv + (size_t)(b * NT + kt * 64 + lrow) * C3 + 2 * NC + h * NHD + c0;
#pragma unroll
        for (int i = 0; i < 4; i++) {
            float4 pv = *reinterpret_cast<const float4*>(pp + 4 * i);
            float4 vv = *reinterpret_cast<const float4*>(vp + 4 * i);
            Ps[lrow][c0 + 4 * i + 0] = pv.x; Ps[lrow][c0 + 4 * i + 1] = pv.y;
            Ps[lrow][c0 + 4 * i + 2] = pv.z; Ps[lrow][c0 + 4 * i + 3] = pv.w;
            Vs[lrow][c0 + 4 * i + 0] = vv.x; Vs[lrow][c0 + 4 * i + 1] = vv.y;
            Vs[lrow][c0 + 4 * i + 2] = vv.z; Vs[lrow][c0 + 4 * i + 3] = vv.w;
        }
        __syncthreads();
#pragma unroll
        for (int kk = 0; kk < 64; kk++) {
            float ar[4], br[4];
#pragma unroll
            for (int i = 0; i < 4; i++) ar[i] = Ps[tr * 4 + i][kk];
            float4 bv = *reinterpret_cast<const float4*>(&Vs[kk][tc * 4]);
            br[0] = bv.x; br[1] = bv.y; br[2] = bv.z; br[3] = bv.w;
#pragma unroll
            for (int i = 0; i < 4; i++)
#pragma unroll
                for (int j = 0; j < 4; j++) acc[i][j] += ar[i] * br[j];
        }
        __syncthreads();
    }
#pragma unroll
    for (int i = 0; i < 4; i++) {
        __half* dst = y + (size_t)(b * NT + qt * 64 + tr * 4 + i) * NC + h * NHD + tc * 4;
#pragma unroll
        for (int j = 0; j < 2; j++) {
            reinterpret_cast<__half2*>(dst)[j] =
                __floats2half2_rn(acc[i][2 * j], acc[i][2 * j + 1]);
        }
    }
}

// ---------------- host orchestration -----------------------------------------
extern "C" void kernel_launch(void* const* d_in, const int* in_sizes, int n_in,
                              void* d_out, int out_size) {
    const int*   ids    = (const int*)  d_in[0];
    const float* wte    = (const float*)d_in[1];
    const float* wpe    = (const float*)d_in[2];
    const float* ln1_w  = (const float*)d_in[3];
    const float* ln1_b  = (const float*)d_in[4];
    const float* attn_w = (const float*)d_in[5];
    const float* attn_b = (const float*)d_in[6];
    const float* proj_w = (const float*)d_in[7];
    const float* proj_b = (const float*)d_in[8];
    const float* ln2_w  = (const float*)d_in[9];
    const float* ln2_b  = (const float*)d_in[10];
    const float* fc_w   = (const float*)d_in[11];
    const float* fc_b   = (const float*)d_in[12];
    const float* fc2_w  = (const float*)d_in[13];
    const float* fc2_b  = (const float*)d_in[14];
    const float* lnf_w  = (const float*)d_in[15];
    const float* lnf_b  = (const float*)d_in[16];
    float* out = (float*)d_out;

    float  *x, *qkv, *att;
    __half *h16, *y16, *mlp16, *wa16, *wp16, *wf16, *wf216, *wte16;
    cudaGetSymbolAddress((void**)&x,     g_x);
    cudaGetSymbolAddress((void**)&qkv,   g_qkv);
    cudaGetSymbolAddress((void**)&att,   g_att);
    cudaGetSymbolAddress((void**)&h16,   g_h16);
    cudaGetSymbolAddress((void**)&y16,   g_y16);
    cudaGetSymbolAddress((void**)&mlp16, g_mlp16);
    cudaGetSymbolAddress((void**)&wa16,  w16_attn);
    cudaGetSymbolAddress((void**)&wp16,  w16_proj);
    cudaGetSymbolAddress((void**)&wf16,  w16_fc);
    cudaGetSymbolAddress((void**)&wf216, w16_fc2);
    cudaGetSymbolAddress((void**)&wte16, w16_wte);

    // weight conversion (once per launch; graph-captured)
    {
        size_t n;
        n = (size_t)NL * NC * C3;  cvt_f2h<<<(int)(n / 4 / 256), 256>>>(attn_w, wa16, (int)(n / 4));
        n = (size_t)NL * NC * NC;  cvt_f2h<<<(int)(n / 4 / 256), 256>>>(proj_w, wp16, (int)(n / 4));
        n = (size_t)NL * NC * C4;  cvt_f2h<<<(int)(n / 4 / 256), 256>>>(fc_w,   wf16, (int)(n / 4));
        n = (size_t)NL * C4 * NC;  cvt_f2h<<<(int)(n / 4 / 256), 256>>>(fc2_w,  wf216, (int)(n / 4));
        n = (size_t)NV * NC;       cvt_f2h<<<(int)((n / 4 + 255) / 256), 256>>>(wte, wte16, (int)(n / 4));
    }

    embed_kernel<<<NTOK, 256>>>(ids, wte, wpe, x);

    for (int l = 0; l < NL; l++) {
        ln_kernel<<<NTOK, 256>>>(x, ln1_w + (size_t)l * NC, ln1_b + (size_t)l * NC, h16);
        hgemm_nn<0><<<dim3(C3 / 128, NTOK / 128), 256>>>(
            h16, wa16 + (size_t)l * NC * C3, attn_b + (size_t)l * C3, qkv, NTOK, C3, NC);
        attn_scores<<<dim3(NT / 64, NT / 64, NB * NH), 256>>>(qkv, att);
        softmax_kernel<<<NB * NH * NT, 256>>>(att);
        attn_av<<<dim3(NT / 64, NB * NH), 256>>>(att, qkv, y16);
        hgemm_nn<1><<<dim3(NC / 128, NTOK / 128), 256>>>(
            y16, wp16 + (size_t)l * NC * NC, proj_b + (size_t)l * NC, x, NTOK, NC, NC);
        ln_kernel<<<NTOK, 256>>>(x, ln2_w + (size_t)l * NC, ln2_b + (size_t)l * NC, h16);
        hgemm_nn<2><<<dim3(C4 / 128, NTOK / 128), 256>>>(
            h16, wf16 + (size_t)l * NC * C4, fc_b + (size_t)l * C4, mlp16, NTOK, C4, NC);
        hgemm_nn<1><<<dim3(NC / 128, NTOK / 128), 256>>>(
            mlp16, wf216 + (size_t)l * C4 * NC, fc2_b + (size_t)l * NC, x, NTOK, NC, C4);
    }

    ln_kernel<<<NTOK, 256>>>(x, lnf_w, lnf_b, h16);
    hgemm_nt<<<dim3((NV + 127) / 128, NTOK / 128), 256>>>(h16, wte16, out, NTOK, NV, NC);
}

// round 8
// speedup vs baseline: 2.6412x; 1.3095x over previous
#include <cuda_runtime.h>
#include <cuda_fp16.h>
#include <math.h>
#include <stdint.h>

// Problem dims
#define NL   8
#define NB   2
#define NT   1024
#define NC   1024
#define NH   16
#define NHD  64
#define NV   50257
#define NTOK 2048
#define C3   3072
#define C4   4096

// ---------------- scratch ----------------------------------------------------
__device__ float  g_x  [NTOK * NC];      // residual (fp32)
__device__ __half g_qkv16[NTOK * C3];    // qkv (fp16)
__device__ __half g_h16 [NTOK * NC];
__device__ __half g_y16 [NTOK * NC];
__device__ __half g_mlp16[NTOK * C4];
__device__ __half w16_attn[(size_t)NL * NC * C3];
__device__ __half w16_proj[(size_t)NL * NC * NC];
__device__ __half w16_fc  [(size_t)NL * NC * C4];
__device__ __half w16_fc2 [(size_t)NL * C4 * NC];
__device__ __half w16_wte [(size_t)NV * NC];

// ---------------- helpers ----------------------------------------------------
__device__ __forceinline__ void mma_f16(float* d, const uint32_t* a, const uint32_t* b) {
    asm volatile(
        "mma.sync.aligned.m16n8k16.row.col.f32.f16.f16.f32 "
        "{%0,%1,%2,%3}, {%4,%5,%6,%7}, {%8,%9}, {%0,%1,%2,%3};"
        : "+f"(d[0]), "+f"(d[1]), "+f"(d[2]), "+f"(d[3])
        : "r"(a[0]), "r"(a[1]), "r"(a[2]), "r"(a[3]), "r"(b[0]), "r"(b[1]));
}
__device__ __forceinline__ uint32_t h2pack(float lo, float hi) {
    __half2 h = __floats2half2_rn(lo, hi);
    return *reinterpret_cast<uint32_t*>(&h);
}

__device__ __forceinline__ float block_sum(float v) {
    __shared__ float sh[8];
    int lane = threadIdx.x & 31, w = threadIdx.x >> 5;
#pragma unroll
    for (int o = 16; o; o >>= 1) v += __shfl_xor_sync(0xffffffffu, v, o);
    if (lane == 0) sh[w] = v;
    __syncthreads();
    v = sh[0] + sh[1] + sh[2] + sh[3] + sh[4] + sh[5] + sh[6] + sh[7];
    __syncthreads();
    return v;
}

// ---------------- weight conversion ------------------------------------------
__global__ void __launch_bounds__(256) cvt_f2h(const float* __restrict__ in,
                                               __half* __restrict__ out, int n4) {
    int i = blockIdx.x * 256 + threadIdx.x;
    if (i < n4) {
        float4 v = reinterpret_cast<const float4*>(in)[i];
        __half2* o = reinterpret_cast<__half2*>(out) + 2 * (size_t)i;
        o[0] = __floats2half2_rn(v.x, v.y);
        o[1] = __floats2half2_rn(v.z, v.w);
    }
}

// ---------------- embedding / layernorm --------------------------------------
__global__ void embed_kernel(const int* __restrict__ ids,
                             const float* __restrict__ wte,
                             const float* __restrict__ wpe,
                             float* __restrict__ x) {
    int tok = blockIdx.x, t = tok & (NT - 1), id = ids[tok];
    const float* src = wte + (size_t)id * NC;
    const float* pp  = wpe + (size_t)t * NC;
    float* dst = x + (size_t)tok * NC;
    for (int c = threadIdx.x; c < NC; c += blockDim.x) dst[c] = src[c] + pp[c];
}

__global__ void __launch_bounds__(256) ln_kernel(const float* __restrict__ x,
                                                 const float* __restrict__ w,
                                                 const float* __restrict__ b,
                                                 __half* __restrict__ o) {
    int row = blockIdx.x, tid = threadIdx.x;
    const float* xr = x + (size_t)row * NC;
    float v[4]; float s = 0.f;
#pragma unroll
    for (int i = 0; i < 4; i++) { v[i] = xr[tid + 256 * i]; s += v[i]; }
    s = block_sum(s);
    float mean = s * (1.f / NC), s2 = 0.f;
#pragma unroll
    for (int i = 0; i < 4; i++) { float d = v[i] - mean; s2 += d * d; }
    s2 = block_sum(s2);
    float rstd = rsqrtf(s2 * (1.f / NC) + 1e-5f);
    __half* orow = o + (size_t)row * NC;
#pragma unroll
    for (int i = 0; i < 4; i++) {
        int c = tid + 256 * i;
        orow[c] = __float2half((v[i] - mean) * rstd * w[c] + b[c]);
    }
}

// =============================================================================
// FP16 GEMM (m16n8k16, fp32 accum). 128x128 tile, KC=32, double-buffered.
// EPI: 0 fp32 store, 1 fp32 residual add, 2 GELU->fp16, 3 store fp16
// =============================================================================
template <int EPI>
__global__ void __launch_bounds__(256) hgemm_nn(const __half* __restrict__ A,
                                                const __half* __restrict__ B,
                                                const float* __restrict__ bias,
                                                void* __restrict__ Dv,
                                                int M, int N, int K) {
    __shared__ uint32_t smA[2][2048];
    __shared__ uint32_t smB[2][2048];

    const int tid  = threadIdx.x;
    const int lane = tid & 31;
    const int warp = tid >> 5;
    const int wm   = warp >> 2;
    const int wn   = warp & 3;
    const int bx = blockIdx.x, by = blockIdx.y;

    const int ar = tid >> 1;
    const int as2 = tid & 1;
    const int abase = as2 * 1024 + (ar >> 4) * 128 + (ar & 7) * 16 + ((ar >> 3) & 1);
    const __half* Ag = A + (size_t)(by * 128 + ar) * K + as2 * 16;

    const int bkp = tid >> 5;
    const int bn0 = (tid & 31) * 4;
    const __half* Bg = B + bx * 128 + bn0;
    int bst[4];
#pragma unroll
    for (int i = 0; i < 4; i++) {
        int n = bn0 + i;
        bst[i] = (n >> 3) * 64 + ((n & 7) * 4 + (bkp & 3)) * 2 + (bkp >> 2);
    }

    float acc[4][4][4];
#pragma unroll
    for (int i = 0; i < 4; i++)
#pragma unroll
        for (int j = 0; j < 4; j++)
#pragma unroll
            for (int r = 0; r < 4; r++) acc[i][j][r] = 0.f;

    const int KT = K >> 5;
    uint4 pa0, pa1;
    uint2 pb[2][2];

    pa0 = *reinterpret_cast<const uint4*>(Ag);
    pa1 = *reinterpret_cast<const uint4*>(Ag + 8);
#pragma unroll
    for (int s2 = 0; s2 < 2; s2++) {
        pb[s2][0] = *reinterpret_cast<const uint2*>(Bg + (size_t)(s2 * 16 + 2 * bkp) * N);
        pb[s2][1] = *reinterpret_cast<const uint2*>(Bg + (size_t)(s2 * 16 + 2 * bkp + 1) * N);
    }
    {
        const uint32_t* aw = reinterpret_cast<const uint32_t*>(&pa0);
#pragma unroll
        for (int jj = 0; jj < 4; jj++) smA[0][abase + jj * 4] = aw[jj];
        aw = reinterpret_cast<const uint32_t*>(&pa1);
#pragma unroll
        for (int jj = 0; jj < 4; jj++) smA[0][abase + jj * 4 + 2] = aw[jj];
#pragma unroll
        for (int s2 = 0; s2 < 2; s2++) {
            smB[0][s2 * 1024 + bst[0]] = __byte_perm(pb[s2][0].x, pb[s2][1].x, 0x5410);
            smB[0][s2 * 1024 + bst[1]] = __byte_perm(pb[s2][0].x, pb[s2][1].x, 0x7632);
            smB[0][s2 * 1024 + bst[2]] = __byte_perm(pb[s2][0].y, pb[s2][1].y, 0x5410);
            smB[0][s2 * 1024 + bst[3]] = __byte_perm(pb[s2][0].y, pb[s2][1].y, 0x7632);
        }
    }
    __syncthreads();

    for (int kt = 0; kt < KT; kt++) {
        const int s = kt & 1;
        if (kt + 1 < KT) {
            const __half* Ap = Ag + (size_t)(kt + 1) * 32;
            pa0 = *reinterpret_cast<const uint4*>(Ap);
            pa1 = *reinterpret_cast<const uint4*>(Ap + 8);
            const __half* Bp = Bg + (size_t)(kt + 1) * 32 * N;
#pragma unroll
            for (int s2 = 0; s2 < 2; s2++) {
                pb[s2][0] = *reinterpret_cast<const uint2*>(Bp + (size_t)(s2 * 16 + 2 * bkp) * N);
                pb[s2][1] = *reinterpret_cast<const uint2*>(Bp + (size_t)(s2 * 16 + 2 * bkp + 1) * N);
            }
        }
#pragma unroll
        for (int s2 = 0; s2 < 2; s2++) {
            uint32_t af[4][4], bf[4][2];
#pragma unroll
            for (int mt = 0; mt < 4; mt++)
                *reinterpret_cast<uint4*>(af[mt]) =
                    *reinterpret_cast<const uint4*>(&smA[s][s2 * 1024 + (wm * 4 + mt) * 128 + lane * 4]);
#pragma unroll
            for (int nt = 0; nt < 4; nt++)
                *reinterpret_cast<uint2*>(bf[nt]) =
                    *reinterpret_cast<const uint2*>(&smB[s][s2 * 1024 + (wn * 4 + nt) * 64 + lane * 2]);
#pragma unroll
            for (int mt = 0; mt < 4; mt++)
#pragma unroll
                for (int nt = 0; nt < 4; nt++)
                    mma_f16(acc[mt][nt], af[mt], bf[nt]);
        }
        if (kt + 1 < KT) {
            const int ns = s ^ 1;
            const uint32_t* aw = reinterpret_cast<const uint32_t*>(&pa0);
#pragma unroll
            for (int jj = 0; jj < 4; jj++) smA[ns][abase + jj * 4] = aw[jj];
            aw = reinterpret_cast<const uint32_t*>(&pa1);
#pragma unroll
            for (int jj = 0; jj < 4; jj++) smA[ns][abase + jj * 4 + 2] = aw[jj];
#pragma unroll
            for (int s2 = 0; s2 < 2; s2++) {
                smB[ns][s2 * 1024 + bst[0]] = __byte_perm(pb[s2][0].x, pb[s2][1].x, 0x5410);
                smB[ns][s2 * 1024 + bst[1]] = __byte_perm(pb[s2][0].x, pb[s2][1].x, 0x7632);
                smB[ns][s2 * 1024 + bst[2]] = __byte_perm(pb[s2][0].y, pb[s2][1].y, 0x5410);
                smB[ns][s2 * 1024 + bst[3]] = __byte_perm(pb[s2][0].y, pb[s2][1].y, 0x7632);
            }
        }
        __syncthreads();
    }

#pragma unroll
    for (int mt = 0; mt < 4; mt++) {
        const int row0 = by * 128 + wm * 64 + mt * 16 + (lane >> 2);
#pragma unroll
        for (int nt = 0; nt < 4; nt++) {
            const int col0 = bx * 128 + wn * 32 + nt * 8 + (lane & 3) * 2;
#pragma unroll
            for (int half = 0; half < 2; half++) {
                float v0 = acc[mt][nt][half * 2 + 0] + bias[col0];
                float v1 = acc[mt][nt][half * 2 + 1] + bias[col0 + 1];
                if (EPI == 2 || EPI == 3) {
                    if (EPI == 2) {
                        v0 = 0.5f * v0 * (1.f + erff(v0 * 0.70710678118654752f));
                        v1 = 0.5f * v1 * (1.f + erff(v1 * 0.70710678118654752f));
                    }
                    __half* drow = (__half*)Dv + (size_t)(row0 + half * 8) * N + col0;
                    *reinterpret_cast<__half2*>(drow) = __floats2half2_rn(v0, v1);
                } else {
                    float* drow = (float*)Dv + (size_t)(row0 + half * 8) * N + col0;
                    if (EPI == 1) { v0 += drow[0]; v1 += drow[1]; }
                    drow[0] = v0; drow[1] = v1;
                }
            }
        }
    }
}

// NT variant (lm_head): D = A[M,K] @ B[N,K]^T, fp32 out
__global__ void __launch_bounds__(256) hgemm_nt(const __half* __restrict__ A,
                                                const __half* __restrict__ B,
                                                float* __restrict__ D,
                                                int M, int N, int K) {
    __shared__ uint32_t smA[2][2048];
    __shared__ uint32_t smB[2][2048];

    const int tid  = threadIdx.x;
    const int lane = tid & 31;
    const int warp = tid >> 5;
    const int wm   = warp >> 2;
    const int wn   = warp & 3;
    const int bx = blockIdx.x, by = blockIdx.y;

    const int ar = tid >> 1;
    const int as2 = tid & 1;
    const int abase = as2 * 1024 + (ar >> 4) * 128 + (ar & 7) * 16 + ((ar >> 3) & 1);
    const __half* Ag = A + (size_t)(by * 128 + ar) * K + as2 * 16;

    const int nr = tid >> 1;
    const int gn = bx * 128 + nr;
    const bool nok = (gn < N);
    const __half* Bg = nok ? (B + (size_t)gn * K + as2 * 16) : Ag;
    const int bbase = as2 * 1024 + (nr >> 3) * 64 + (nr & 7) * 8;

    float acc[4][4][4];
#pragma unroll
    for (int i = 0; i < 4; i++)
#pragma unroll
        for (int j = 0; j < 4; j++)
#pragma unroll
            for (int r = 0; r < 4; r++) acc[i][j][r] = 0.f;

    const int KT = K >> 5;
    uint4 pa0, pa1, pb0, pb1;

    pa0 = *reinterpret_cast<const uint4*>(Ag);
    pa1 = *reinterpret_cast<const uint4*>(Ag + 8);
    pb0 = *reinterpret_cast<const uint4*>(Bg);
    pb1 = *reinterpret_cast<const uint4*>(Bg + 8);
    if (!nok) { pb0 = make_uint4(0, 0, 0, 0); pb1 = pb0; }
    {
        const uint32_t* aw = reinterpret_cast<const uint32_t*>(&pa0);
        const uint32_t* bw = reinterpret_cast<const uint32_t*>(&pb0);
#pragma unroll
        for (int jj = 0; jj < 4; jj++) {
            smA[0][abase + jj * 4] = aw[jj];
            smB[0][bbase + jj * 2] = bw[jj];
        }
        aw = reinterpret_cast<const uint32_t*>(&pa1);
        bw = reinterpret_cast<const uint32_t*>(&pb1);
#pragma unroll
        for (int jj = 0; jj < 4; jj++) {
            smA[0][abase + jj * 4 + 2] = aw[jj];
            smB[0][bbase + jj * 2 + 1] = bw[jj];
        }
    }
    __syncthreads();

    for (int kt = 0; kt < KT; kt++) {
        const int s = kt & 1;
        if (kt + 1 < KT) {
            const __half* Ap = Ag + (size_t)(kt + 1) * 32;
            const __half* Bp = Bg + (size_t)(kt + 1) * 32;
            pa0 = *reinterpret_cast<const uint4*>(Ap);
            pa1 = *reinterpret_cast<const uint4*>(Ap + 8);
            pb0 = *reinterpret_cast<const uint4*>(Bp);
            pb1 = *reinterpret_cast<const uint4*>(Bp + 8);
            if (!nok) { pb0 = make_uint4(0, 0, 0, 0); pb1 = pb0; }
        }
#pragma unroll
        for (int s2 = 0; s2 < 2; s2++) {
            uint32_t af[4][4], bf[4][2];
#pragma unroll
            for (int mt = 0; mt < 4; mt++)
                *reinterpret_cast<uint4*>(af[mt]) =
                    *reinterpret_cast<const uint4*>(&smA[s][s2 * 1024 + (wm * 4 + mt) * 128 + lane * 4]);
#pragma unroll
            for (int nt = 0; nt < 4; nt++)
                *reinterpret_cast<uint2*>(bf[nt]) =
                    *reinterpret_cast<const uint2*>(&smB[s][s2 * 1024 + (wn * 4 + nt) * 64 + lane * 2]);
#pragma unroll
            for (int mt = 0; mt < 4; mt++)
#pragma unroll
                for (int nt = 0; nt < 4; nt++)
                    mma_f16(acc[mt][nt], af[mt], bf[nt]);
        }
        if (kt + 1 < KT) {
            const int ns = s ^ 1;
            const uint32_t* aw = reinterpret_cast<const uint32_t*>(&pa0);
            const uint32_t* bw = reinterpret_cast<const uint32_t*>(&pb0);
#pragma unroll
            for (int jj = 0; jj < 4; jj++) {
                smA[ns][abase + jj * 4] = aw[jj];
                smB[ns][bbase + jj * 2] = bw[jj];
            }
            aw = reinterpret_cast<const uint32_t*>(&pa1);
            bw = reinterpret_cast<const uint32_t*>(&pb1);
#pragma unroll
            for (int jj = 0; jj < 4; jj++) {
                smA[ns][abase + jj * 4 + 2] = aw[jj];
                smB[ns][bbase + jj * 2 + 1] = bw[jj];
            }
        }
        __syncthreads();
    }

#pragma unroll
    for (int mt = 0; mt < 4; mt++) {
        const int row0 = by * 128 + wm * 64 + mt * 16 + (lane >> 2);
#pragma unroll
        for (int nt = 0; nt < 4; nt++) {
            const int col0 = bx * 128 + wn * 32 + nt * 8 + (lane & 3) * 2;
#pragma unroll
            for (int half = 0; half < 2; half++) {
                float* drow = D + (size_t)(row0 + half * 8) * N;
                if (col0 < N)     drow[col0]     = acc[mt][nt][half * 2 + 0];
                if (col0 + 1 < N) drow[col0 + 1] = acc[mt][nt][half * 2 + 1];
            }
        }
    }
}

// =============================================================================
// Flash attention (fp16 MMA, fp32 softmax/accum). One block per (qtile=128, b*h).
// =============================================================================
__global__ void __launch_bounds__(256) flash_attn(const __half* __restrict__ qkv,
                                                  __half* __restrict__ y) {
    __shared__ uint32_t sK[2][2048];
    __shared__ uint32_t sV[2][2048];
    uint32_t* sq = &sK[0][0];

    const int tid = threadIdx.x, lane = tid & 31, warp = tid >> 5;
    const int qt = blockIdx.x;
    const int bh = blockIdx.y, b = bh >> 4, h = bh & 15;

    const __half* qbase = qkv + (size_t)(b * NT + qt * 128) * C3 + h * NHD;
    const __half* kbase = qkv + (size_t)(b * NT) * C3 + NC + h * NHD;
    const __half* vbase = qkv + (size_t)(b * NT) * C3 + 2 * NC + h * NHD;

    // ---- stage Q (128x64) into a-frag layout, pull frags to registers ----
    uint32_t af[4][4];
    {
        const int r = tid >> 1, hf = tid & 1;
        const __half* qp = qbase + (size_t)r * C3 + hf * 32;
        uint4 v0 = *reinterpret_cast<const uint4*>(qp);
        uint4 v1 = *reinterpret_cast<const uint4*>(qp + 8);
        uint4 v2 = *reinterpret_cast<const uint4*>(qp + 16);
        uint4 v3 = *reinterpret_cast<const uint4*>(qp + 24);
        const int ab0 = (2 * hf) * 1024 + (r >> 4) * 128 + (r & 7) * 16 + ((r >> 3) & 1);
        const int ab1 = ab0 + 1024;
        const uint32_t* w0 = reinterpret_cast<const uint32_t*>(&v0);
        const uint32_t* w1 = reinterpret_cast<const uint32_t*>(&v1);
        const uint32_t* w2 = reinterpret_cast<const uint32_t*>(&v2);
        const uint32_t* w3 = reinterpret_cast<const uint32_t*>(&v3);
#pragma unroll
        for (int i = 0; i < 4; i++) {
            sq[ab0 + i * 4]     = w0[i];
            sq[ab0 + i * 4 + 2] = w1[i];
            sq[ab1 + i * 4]     = w2[i];
            sq[ab1 + i * 4 + 2] = w3[i];
        }
        __syncthreads();
#pragma unroll
        for (int ks = 0; ks < 4; ks++)
            *reinterpret_cast<uint4*>(af[ks]) =
                *reinterpret_cast<const uint4*>(&sq[ks * 1024 + warp * 128 + lane * 4]);
        __syncthreads();
    }

    const int knr = tid >> 2, kq = tid & 3;
    const int kb  = kq * 512 + (knr >> 3) * 64 + (knr & 7) * 8;
    const int vpp = tid >> 3, vn0 = (tid & 7) * 8;
    const int vks = vpp >> 3, vjj = vpp & 7;
    int vst[4];
#pragma unroll
    for (int i = 0; i < 4; i++) {
        int n = vn0 + 2 * i;
        vst[i] = vks * 512 + (n >> 3) * 64 + ((n & 7) * 4 + (vjj & 3)) * 2 + (vjj >> 2);
    }

    float oacc[8][4];
#pragma unroll
    for (int nt = 0; nt < 8; nt++)
#pragma unroll
        for (int i = 0; i < 4; i++) oacc[nt][i] = 0.f;
    float mrun0 = -1e30f, mrun1 = -1e30f, lrun0 = 0.f, lrun1 = 0.f;

    uint4 ku0, ku1, va, vb;

    {
        const __half* kp = kbase + (size_t)knr * C3 + kq * 16;
        ku0 = *reinterpret_cast<const uint4*>(kp);
        ku1 = *reinterpret_cast<const uint4*>(kp + 8);
        const __half* vp = vbase + (size_t)(2 * vpp) * C3 + vn0;
        va = *reinterpret_cast<const uint4*>(vp);
        vb = *reinterpret_cast<const uint4*>(vp + C3);
        const uint32_t* kw0 = reinterpret_cast<const uint32_t*>(&ku0);
        const uint32_t* kw1 = reinterpret_cast<const uint32_t*>(&ku1);
        const uint32_t* vwa = reinterpret_cast<const uint32_t*>(&va);
        const uint32_t* vwb = reinterpret_cast<const uint32_t*>(&vb);
#pragma unroll
        for (int i = 0; i < 4; i++) {
            sK[0][kb + i * 2]     = kw0[i];
            sK[0][kb + i * 2 + 1] = kw1[i];
            sV[0][vst[i]]     = __byte_perm(vwa[i], vwb[i], 0x5410);
            sV[0][vst[i] + 8] = __byte_perm(vwa[i], vwb[i], 0x7632);   // FIXED: n+1 slot is +8
        }
    }
    __syncthreads();

    for (int kt = 0; kt < 16; kt++) {
        const int s = kt & 1;
        if (kt + 1 < 16) {
            const __half* kp = kbase + (size_t)((kt + 1) * 64 + knr) * C3 + kq * 16;
            ku0 = *reinterpret_cast<const uint4*>(kp);
            ku1 = *reinterpret_cast<const uint4*>(kp + 8);
            const __half* vp = vbase + (size_t)((kt + 1) * 64 + 2 * vpp) * C3 + vn0;
            va = *reinterpret_cast<const uint4*>(vp);
            vb = *reinterpret_cast<const uint4*>(vp + C3);
        }

        float sacc[8][4];
#pragma unroll
        for (int nt = 0; nt < 8; nt++) {
#pragma unroll
            for (int i = 0; i < 4; i++) sacc[nt][i] = 0.f;
#pragma unroll
            for (int ks = 0; ks < 4; ks++) {
                uint32_t bf[2];
                *reinterpret_cast<uint2*>(bf) =
                    *reinterpret_cast<const uint2*>(&sK[s][ks * 512 + nt * 64 + lane * 2]);
                mma_f16(sacc[nt], af[ks], bf);
            }
        }

        float m0 = -1e30f, m1 = -1e30f;
#pragma unroll
        for (int nt = 0; nt < 8; nt++) {
#pragma unroll
            for (int i = 0; i < 4; i++) sacc[nt][i] *= 0.125f;
            m0 = fmaxf(m0, fmaxf(sacc[nt][0], sacc[nt][1]));
            m1 = fmaxf(m1, fmaxf(sacc[nt][2], sacc[nt][3]));
        }
        m0 = fmaxf(m0, __shfl_xor_sync(0xffffffffu, m0, 1));
        m0 = fmaxf(m0, __shfl_xor_sync(0xffffffffu, m0, 2));
        m1 = fmaxf(m1, __shfl_xor_sync(0xffffffffu, m1, 1));
        m1 = fmaxf(m1, __shfl_xor_sync(0xffffffffu, m1, 2));
        const float mn0 = fmaxf(mrun0, m0), mn1 = fmaxf(mrun1, m1);
        const float al0 = __expf(mrun0 - mn0), al1 = __expf(mrun1 - mn1);
        mrun0 = mn0; mrun1 = mn1;

        float r0 = 0.f, r1 = 0.f;
#pragma unroll
        for (int nt = 0; nt < 8; nt++) {
            sacc[nt][0] = __expf(sacc[nt][0] - mn0);
            sacc[nt][1] = __expf(sacc[nt][1] - mn0);
            sacc[nt][2] = __expf(sacc[nt][2] - mn1);
            sacc[nt][3] = __expf(sacc[nt][3] - mn1);
            r0 += sacc[nt][0] + sacc[nt][1];
            r1 += sacc[nt][2] + sacc[nt][3];
        }
        r0 += __shfl_xor_sync(0xffffffffu, r0, 1);
        r0 += __shfl_xor_sync(0xffffffffu, r0, 2);
        r1 += __shfl_xor_sync(0xffffffffu, r1, 1);
        r1 += __shfl_xor_sync(0xffffffffu, r1, 2);
        lrun0 = lrun0 * al0 + r0;
        lrun1 = lrun1 * al1 + r1;

#pragma unroll
        for (int nt = 0; nt < 8; nt++) {
            oacc[nt][0] *= al0; oacc[nt][1] *= al0;
            oacc[nt][2] *= al1; oacc[nt][3] *= al1;
        }

        uint32_t pf[4][4];
#pragma unroll
        for (int ks = 0; ks < 4; ks++) {
            pf[ks][0] = h2pack(sacc[2 * ks][0],     sacc[2 * ks][1]);
            pf[ks][1] = h2pack(sacc[2 * ks][2],     sacc[2 * ks][3]);
            pf[ks][2] = h2pack(sacc[2 * ks + 1][0], sacc[2 * ks + 1][1]);
            pf[ks][3] = h2pack(sacc[2 * ks + 1][2], sacc[2 * ks + 1][3]);
        }
#pragma unroll
        for (int nt = 0; nt < 8; nt++) {
#pragma unroll
            for (int ks = 0; ks < 4; ks++) {
                uint32_t bf[2];
                *reinterpret_cast<uint2*>(bf) =
                    *reinterpret_cast<const uint2*>(&sV[s][ks * 512 + nt * 64 + lane * 2]);
                mma_f16(oacc[nt], pf[ks], bf);
            }
        }

        if (kt + 1 < 16) {
            const int ns = s ^ 1;
            const uint32_t* kw0 = reinterpret_cast<const uint32_t*>(&ku0);
            const uint32_t* kw1 = reinterpret_cast<const uint32_t*>(&ku1);
            const uint32_t* vwa = reinterpret_cast<const uint32_t*>(&va);
            const uint32_t* vwb = reinterpret_cast<const uint32_t*>(&vb);
#pragma unroll
            for (int i = 0; i < 4; i++) {
                sK[ns][kb + i * 2]     = kw0[i];
                sK[ns][kb + i * 2 + 1] = kw1[i];
                sV[ns][vst[i]]     = __byte_perm(vwa[i], vwb[i], 0x5410);
                sV[ns][vst[i] + 8] = __byte_perm(vwa[i], vwb[i], 0x7632);   // FIXED
            }
        }
        __syncthreads();
    }

    const float inv0 = 1.f / lrun0, inv1 = 1.f / lrun1;
    const int r0g = qt * 128 + warp * 16 + (lane >> 2);
    __half* y0 = y + (size_t)(b * NT + r0g) * NC + h * NHD + (lane & 3) * 2;
    __half* y1 = y0 + 8 * NC;
#pragma unroll
    for (int nt = 0; nt < 8; nt++) {
        *reinterpret_cast<__half2*>(y0 + nt * 8) =
            __floats2half2_rn(oacc[nt][0] * inv0, oacc[nt][1] * inv0);
        *reinterpret_cast<__half2*>(y1 + nt * 8) =
            __floats2half2_rn(oacc[nt][2] * inv1, oacc[nt][3] * inv1);
    }
}

// ---------------- host orchestration -----------------------------------------
extern "C" void kernel_launch(void* const* d_in, const int* in_sizes, int n_in,
                              void* d_out, int out_size) {
    const int*   ids    = (const int*)  d_in[0];
    const float* wte    = (const float*)d_in[1];
    const float* wpe    = (const float*)d_in[2];
    const float* ln1_w  = (const float*)d_in[3];
    const float* ln1_b  = (const float*)d_in[4];
    const float* attn_w = (const float*)d_in[5];
    const float* attn_b = (const float*)d_in[6];
    const float* proj_w = (const float*)d_in[7];
    const float* proj_b = (const float*)d_in[8];
    const float* ln2_w  = (const float*)d_in[9];
    const float* ln2_b  = (const float*)d_in[10];
    const float* fc_w   = (const float*)d_in[11];
    const float* fc_b   = (const float*)d_in[12];
    const float* fc2_w  = (const float*)d_in[13];
    const float* fc2_b  = (const float*)d_in[14];
    const float* lnf_w  = (const float*)d_in[15];
    const float* lnf_b  = (const float*)d_in[16];
    float* out = (float*)d_out;

    float  *x;
    __half *qkv16, *h16, *y16, *mlp16, *wa16, *wp16, *wf16, *wf216, *wte16;
    cudaGetSymbolAddress((void**)&x,     g_x);
    cudaGetSymbolAddress((void**)&qkv16, g_qkv16);
    cudaGetSymbolAddress((void**)&h16,   g_h16);
    cudaGetSymbolAddress((void**)&y16,   g_y16);
    cudaGetSymbolAddress((void**)&mlp16, g_mlp16);
    cudaGetSymbolAddress((void**)&wa16,  w16_attn);
    cudaGetSymbolAddress((void**)&wp16,  w16_proj);
    cudaGetSymbolAddress((void**)&wf16,  w16_fc);
    cudaGetSymbolAddress((void**)&wf216, w16_fc2);
    cudaGetSymbolAddress((void**)&wte16, w16_wte);

    {
        size_t n;
        n = (size_t)NL * NC * C3;  cvt_f2h<<<(int)(n / 4 / 256), 256>>>(attn_w, wa16, (int)(n / 4));
        n = (size_t)NL * NC * NC;  cvt_f2h<<<(int)(n / 4 / 256), 256>>>(proj_w, wp16, (int)(n / 4));
        n = (size_t)NL * NC * C4;  cvt_f2h<<<(int)(n / 4 / 256), 256>>>(fc_w,   wf16, (int)(n / 4));
        n = (size_t)NL * C4 * NC;  cvt_f2h<<<(int)(n / 4 / 256), 256>>>(fc2_w,  wf216, (int)(n / 4));
        n = (size_t)NV * NC;       cvt_f2h<<<(int)((n / 4 + 255) / 256), 256>>>(wte, wte16, (int)(n / 4));
    }

    embed_kernel<<<NTOK, 256>>>(ids, wte, wpe, x);

    for (int l = 0; l < NL; l++) {
        ln_kernel<<<NTOK, 256>>>(x, ln1_w + (size_t)l * NC, ln1_b + (size_t)l * NC, h16);
        hgemm_nn<3><<<dim3(C3 / 128, NTOK / 128), 256>>>(
            h16, wa16 + (size_t)l * NC * C3, attn_b + (size_t)l * C3, qkv16, NTOK, C3, NC);
        flash_attn<<<dim3(NT / 128, NB * NH), 256>>>(qkv16, y16);
        hgemm_nn<1><<<dim3(NC / 128, NTOK / 128), 256>>>(
            y16, wp16 + (size_t)l * NC * NC, proj_b + (size_t)l * NC, x, NTOK, NC, NC);
        ln_kernel<<<NTOK, 256>>>(x, ln2_w + (size_t)l * NC, ln2_b + (size_t)l * NC, h16);
        hgemm_nn<2><<<dim3(C4 / 128, NTOK / 128), 256>>>(
            h16, wf16 + (size_t)l * NC * C4, fc_b + (size_t)l * C4, mlp16, NTOK, C4, NC);
        hgemm_nn<1><<<dim3(NC / 128, NTOK / 128), 256>>>(
            mlp16, wf216 + (size_t)l * C4 * NC, fc2_b + (size_t)l * NC, x, NTOK, NC, C4);
    }

    ln_kernel<<<NTOK, 256>>>(x, lnf_w, lnf_b, h16);
    hgemm_nt<<<dim3((NV + 127) / 128, NTOK / 128), 256>>>(h16, wte16, out, NTOK, NV, NC);
}

// round 9
// speedup vs baseline: 7.4855x; 2.8341x over previous
#include <cuda_runtime.h>
#include <cuda_fp16.h>
#include <math.h>
#include <stdint.h>

// Problem dims
#define NL   8
#define NB   2
#define NT   1024
#define NC   1024
#define NH   16
#define NHD  64
#define NV   50257
#define NVP  50304          // padded to 393*128
#define NTOK 2048
#define C3   3072
#define C4   4096

// ---------------- scratch ----------------------------------------------------
__device__ float    g_x    [NTOK * NC];            // residual (fp32)
__device__ __half   g_qkv16[NTOK * C3];            // qkv (fp16 row-major, flash input)
__device__ uint32_t g_h16t [NTOK * NC / 2];        // LN out, A-fragment-tiled
__device__ uint32_t g_y16t [NTOK * NC / 2];        // attn out, A-tiled
__device__ uint32_t g_mlp16t[NTOK * C4 / 2];       // GELU out, A-tiled
// fragment-tiled fp16 weights (built once per launch)
__device__ uint32_t w_attn_t[(size_t)NL * NC * C3 / 2];
__device__ uint32_t w_proj_t[(size_t)NL * NC * NC / 2];
__device__ uint32_t w_fc_t  [(size_t)NL * NC * C4 / 2];
__device__ uint32_t w_fc2_t [(size_t)NL * C4 * NC / 2];
__device__ uint32_t w_wte_t [(size_t)NVP * NC / 2];

// ---------------- helpers ----------------------------------------------------
__device__ __forceinline__ void mma_f16(float* d, const uint32_t* a, const uint32_t* b) {
    asm volatile(
        "mma.sync.aligned.m16n8k16.row.col.f32.f16.f16.f32 "
        "{%0,%1,%2,%3}, {%4,%5,%6,%7}, {%8,%9}, {%0,%1,%2,%3};"
        : "+f"(d[0]), "+f"(d[1]), "+f"(d[2]), "+f"(d[3])
        : "r"(a[0]), "r"(a[1]), "r"(a[2]), "r"(a[3]), "r"(b[0]), "r"(b[1]));
}
__device__ __forceinline__ uint32_t h2pack(float lo, float hi) {
    __half2 h = __floats2half2_rn(lo, hi);
    return *reinterpret_cast<uint32_t*>(&h);
}
__device__ __forceinline__ uint32_t smem_u32(const void* p) {
    uint32_t a;
    asm("{ .reg .u64 t; cvta.to.shared.u64 t, %1; cvt.u32.u64 %0, t; }" : "=r"(a) : "l"(p));
    return a;
}
#define CP_ASYNC16(dst, src) \
    asm volatile("cp.async.cg.shared.global [%0], [%1], 16;" :: "r"(dst), "l"(src))
#define CP_COMMIT() asm volatile("cp.async.commit_group;" ::: "memory")
#define CP_WAIT2()  asm volatile("cp.async.wait_group 2;" ::: "memory")

// A-fragment-tiled word index for pair (col even): word holds halves (col, col+1)
__device__ __forceinline__ size_t a_widx(int row, int col, int KB) {
    return ((size_t)(row >> 7) * KB + (col >> 4)) * 1024
         + ((row >> 4) & 7) * 128 + (row & 7) * 16 + ((row >> 3) & 1)
         + ((col >> 1) & 3) * 4 + ((col >> 3) & 1) * 2;
}

__device__ __forceinline__ float block_sum(float v) {
    __shared__ float sh[8];
    int lane = threadIdx.x & 31, w = threadIdx.x >> 5;
#pragma unroll
    for (int o = 16; o; o >>= 1) v += __shfl_xor_sync(0xffffffffu, v, o);
    if (lane == 0) sh[w] = v;
    __syncthreads();
    v = sh[0] + sh[1] + sh[2] + sh[3] + sh[4] + sh[5] + sh[6] + sh[7];
    __syncthreads();
    return v;
}

// ---------------- weight conversion to fragment-tiled layout ------------------
// NN weights: in[k][n] row-major (K x N) -> per layer [ntile][kblock][1024]
__global__ void __launch_bounds__(256) cvt_w_nn(const float* __restrict__ in,
                                                uint32_t* __restrict__ out,
                                                int K, int N) {
    const int nt = blockIdx.x, kb = blockIdx.y, l = blockIdx.z;
    const float* src = in + (size_t)l * K * N;
    uint32_t* dst = out + (((size_t)l * (N >> 7) + nt) * (K >> 4) + kb) * 1024;
    const int t = threadIdx.x;
#pragma unroll
    for (int w = 0; w < 4; w++) {
        int wid = t + 256 * w;
        int jj = wid >> 7, n = wid & 127;
        int k = kb * 16 + 2 * jj;
        int gn = nt * 128 + n;
        float lo = src[(size_t)k * N + gn];
        float hi = src[(size_t)(k + 1) * N + gn];
        dst[(n >> 3) * 64 + (n & 7) * 8 + (jj & 3) * 2 + (jj >> 2)] = h2pack(lo, hi);
    }
}

// wte (NT): in[n][k] row-major (NV x NC) -> [ntile][kblock][1024], zero-padded rows
__global__ void __launch_bounds__(256) cvt_wte_nt(const float* __restrict__ in,
                                                  uint32_t* __restrict__ out) {
    const int nt = blockIdx.x, kb = blockIdx.y;
    uint32_t* dst = out + ((size_t)nt * (NC >> 4) + kb) * 1024;
    const int t = threadIdx.x;
#pragma unroll
    for (int w = 0; w < 4; w++) {
        int wid = t + 256 * w;
        int nr = wid >> 3, jj = wid & 7;
        int gn = nt * 128 + nr;
        int k = kb * 16 + 2 * jj;
        float lo = 0.f, hi = 0.f;
        if (gn < NV) {
            lo = in[(size_t)gn * NC + k];
            hi = in[(size_t)gn * NC + k + 1];
        }
        dst[(nr >> 3) * 64 + (nr & 7) * 8 + (jj & 3) * 2 + (jj >> 2)] = h2pack(lo, hi);
    }
}

// ---------------- embedding / layernorm --------------------------------------
__global__ void embed_kernel(const int* __restrict__ ids,
                             const float* __restrict__ wte,
                             const float* __restrict__ wpe,
                             float* __restrict__ x) {
    int tok = blockIdx.x, t = tok & (NT - 1), id = ids[tok];
    const float* src = wte + (size_t)id * NC;
    const float* pp  = wpe + (size_t)t * NC;
    float* dst = x + (size_t)tok * NC;
    for (int c = threadIdx.x; c < NC; c += blockDim.x) dst[c] = src[c] + pp[c];
}

// layernorm -> A-fragment-tiled fp16 (KB = 64 for K=1024)
__global__ void __launch_bounds__(256) ln_kernel(const float* __restrict__ x,
                                                 const float* __restrict__ w,
                                                 const float* __restrict__ b,
                                                 uint32_t* __restrict__ o) {
    int row = blockIdx.x, tid = threadIdx.x;
    const float2* xr = reinterpret_cast<const float2*>(x + (size_t)row * NC);
    float2 v[2]; float s = 0.f;
#pragma unroll
    for (int i = 0; i < 2; i++) { v[i] = xr[tid + 256 * i]; s += v[i].x + v[i].y; }
    s = block_sum(s);
    float mean = s * (1.f / NC), s2 = 0.f;
#pragma unroll
    for (int i = 0; i < 2; i++) {
        float dx = v[i].x - mean, dy = v[i].y - mean;
        s2 += dx * dx + dy * dy;
    }
    s2 = block_sum(s2);
    float rstd = rsqrtf(s2 * (1.f / NC) + 1e-5f);
#pragma unroll
    for (int i = 0; i < 2; i++) {
        int col = 2 * (tid + 256 * i);
        float a0 = (v[i].x - mean) * rstd * w[col] + b[col];
        float a1 = (v[i].y - mean) * rstd * w[col + 1] + b[col + 1];
        o[a_widx(row, col, 64)] = h2pack(a0, a1);
    }
}

// =============================================================================
// Unified fragment-tiled FP16 GEMM with cp.async 4-stage pipeline.
// A: [M/128][KB][1024] tiled.  B: [ntile][KB][1024] tiled (NN and NT share layout).
// 128x128 tile, KC=32 (2 k16-blocks) per stage. 256 threads, warp tile 64x32.
// EPI: 1 fp32 residual add (+bias)   2 GELU -> tiled fp16 (+bias)
//      3 fp16 row-major (+bias)      4 fp32 store, no bias, col<N guard
// =============================================================================
template <int EPI>
__global__ void __launch_bounds__(256) hgemm_t(const uint32_t* __restrict__ At,
                                               const uint32_t* __restrict__ Bt,
                                               const float* __restrict__ bias,
                                               void* __restrict__ Dv,
                                               int N, int KB) {
    extern __shared__ uint32_t dsm[];
    const int tid = threadIdx.x, lane = tid & 31, warp = tid >> 5;
    const int wm = warp >> 2, wn = warp & 3;
    const int bx = blockIdx.x, by = blockIdx.y;
    const uint32_t sb = smem_u32(dsm);

    const uint32_t* Asrc = At + (size_t)by * KB * 1024;
    const uint32_t* Bsrc = Bt + (size_t)bx * KB * 1024;
    const int KT = KB >> 1;

    auto issue = [&](int st, int kt2) {
        uint32_t d = sb + st * 16384 + tid * 16;
        const uint32_t* sa = Asrc + (size_t)kt2 * 2048 + tid * 4;
        const uint32_t* sbp = Bsrc + (size_t)kt2 * 2048 + tid * 4;
        CP_ASYNC16(d,         sa);
        CP_ASYNC16(d + 4096,  sa + 1024);
        CP_ASYNC16(d + 8192,  sbp);
        CP_ASYNC16(d + 12288, sbp + 1024);
    };

    // prologue: 3 stages in flight
    for (int p = 0; p < 3; p++) { if (p < KT) issue(p, p); CP_COMMIT(); }

    float acc[4][4][4];
#pragma unroll
    for (int i = 0; i < 4; i++)
#pragma unroll
        for (int j = 0; j < 4; j++)
#pragma unroll
            for (int r = 0; r < 4; r++) acc[i][j][r] = 0.f;

    for (int kt = 0; kt < KT; kt++) {
        const int st = kt & 3;
        CP_WAIT2();
        __syncthreads();
        if (kt + 3 < KT) issue((kt + 3) & 3, kt + 3);
        CP_COMMIT();
#pragma unroll
        for (int s2 = 0; s2 < 2; s2++) {
            const uint32_t* As = dsm + st * 4096 + s2 * 1024;
            const uint32_t* Bs = dsm + st * 4096 + 2048 + s2 * 1024;
            uint32_t af[4][4], bf[4][2];
#pragma unroll
            for (int mt = 0; mt < 4; mt++)
                *reinterpret_cast<uint4*>(af[mt]) =
                    *reinterpret_cast<const uint4*>(&As[(wm * 4 + mt) * 128 + lane * 4]);
#pragma unroll
            for (int nt = 0; nt < 4; nt++)
                *reinterpret_cast<uint2*>(bf[nt]) =
                    *reinterpret_cast<const uint2*>(&Bs[(wn * 4 + nt) * 64 + lane * 2]);
#pragma unroll
            for (int mt = 0; mt < 4; mt++)
#pragma unroll
                for (int nt = 0; nt < 4; nt++)
                    mma_f16(acc[mt][nt], af[mt], bf[nt]);
        }
    }

    // epilogue
#pragma unroll
    for (int mt = 0; mt < 4; mt++) {
        const int row0 = by * 128 + wm * 64 + mt * 16 + (lane >> 2);
#pragma unroll
        for (int nt = 0; nt < 4; nt++) {
            const int col0 = bx * 128 + wn * 32 + nt * 8 + (lane & 3) * 2;
#pragma unroll
            for (int hf = 0; hf < 2; hf++) {
                const int row = row0 + hf * 8;
                float v0 = acc[mt][nt][hf * 2 + 0];
                float v1 = acc[mt][nt][hf * 2 + 1];
                if (EPI != 4) { v0 += bias[col0]; v1 += bias[col0 + 1]; }
                if (EPI == 1) {
                    float* drow = (float*)Dv + (size_t)row * N + col0;
                    drow[0] += v0; drow[1] += v1;
                } else if (EPI == 2) {
                    v0 = 0.5f * v0 * (1.f + erff(v0 * 0.70710678118654752f));
                    v1 = 0.5f * v1 * (1.f + erff(v1 * 0.70710678118654752f));
                    ((uint32_t*)Dv)[a_widx(row, col0, N >> 4)] = h2pack(v0, v1);
                } else if (EPI == 3) {
                    __half* drow = (__half*)Dv + (size_t)row * N + col0;
                    *reinterpret_cast<__half2*>(drow) = __floats2half2_rn(v0, v1);
                } else {  // EPI == 4
                    float* drow = (float*)Dv + (size_t)row * N;
                    if (col0 < N)     drow[col0]     = v0;
                    if (col0 + 1 < N) drow[col0 + 1] = v1;
                }
            }
        }
    }
}

// =============================================================================
// Flash attention (fp16 MMA, fp32 softmax/accum) — unchanged core, tiled y out.
// =============================================================================
__global__ void __launch_bounds__(256) flash_attn(const __half* __restrict__ qkv,
                                                  uint32_t* __restrict__ yt) {
    __shared__ uint32_t sK[2][2048];
    __shared__ uint32_t sV[2][2048];
    uint32_t* sq = &sK[0][0];

    const int tid = threadIdx.x, lane = tid & 31, warp = tid >> 5;
    const int qt = blockIdx.x;
    const int bh = blockIdx.y, b = bh >> 4, h = bh & 15;

    const __half* qbase = qkv + (size_t)(b * NT + qt * 128) * C3 + h * NHD;
    const __half* kbase = qkv + (size_t)(b * NT) * C3 + NC + h * NHD;
    const __half* vbase = qkv + (size_t)(b * NT) * C3 + 2 * NC + h * NHD;

    uint32_t af[4][4];
    {
        const int r = tid >> 1, hfq = tid & 1;
        const __half* qp = qbase + (size_t)r * C3 + hfq * 32;
        uint4 v0 = *reinterpret_cast<const uint4*>(qp);
        uint4 v1 = *reinterpret_cast<const uint4*>(qp + 8);
        uint4 v2 = *reinterpret_cast<const uint4*>(qp + 16);
        uint4 v3 = *reinterpret_cast<const uint4*>(qp + 24);
        const int ab0 = (2 * hfq) * 1024 + (r >> 4) * 128 + (r & 7) * 16 + ((r >> 3) & 1);
        const int ab1 = ab0 + 1024;
        const uint32_t* w0 = reinterpret_cast<const uint32_t*>(&v0);
        const uint32_t* w1 = reinterpret_cast<const uint32_t*>(&v1);
        const uint32_t* w2 = reinterpret_cast<const uint32_t*>(&v2);
        const uint32_t* w3 = reinterpret_cast<const uint32_t*>(&v3);
#pragma unroll
        for (int i = 0; i < 4; i++) {
            sq[ab0 + i * 4]     = w0[i];
            sq[ab0 + i * 4 + 2] = w1[i];
            sq[ab1 + i * 4]     = w2[i];
            sq[ab1 + i * 4 + 2] = w3[i];
        }
        __syncthreads();
#pragma unroll
        for (int ks = 0; ks < 4; ks++)
            *reinterpret_cast<uint4*>(af[ks]) =
                *reinterpret_cast<const uint4*>(&sq[ks * 1024 + warp * 128 + lane * 4]);
        __syncthreads();
    }

    const int knr = tid >> 2, kq = tid & 3;
    const int kb  = kq * 512 + (knr >> 3) * 64 + (knr & 7) * 8;
    const int vpp = tid >> 3, vn0 = (tid & 7) * 8;
    const int vks = vpp >> 3, vjj = vpp & 7;
    int vst[4];
#pragma unroll
    for (int i = 0; i < 4; i++) {
        int n = vn0 + 2 * i;
        vst[i] = vks * 512 + (n >> 3) * 64 + ((n & 7) * 4 + (vjj & 3)) * 2 + (vjj >> 2);
    }

    float oacc[8][4];
#pragma unroll
    for (int nt = 0; nt < 8; nt++)
#pragma unroll
        for (int i = 0; i < 4; i++) oacc[nt][i] = 0.f;
    float mrun0 = -1e30f, mrun1 = -1e30f, lrun0 = 0.f, lrun1 = 0.f;

    uint4 ku0, ku1, va, vb;
    {
        const __half* kp = kbase + (size_t)knr * C3 + kq * 16;
        ku0 = *reinterpret_cast<const uint4*>(kp);
        ku1 = *reinterpret_cast<const uint4*>(kp + 8);
        const __half* vp = vbase + (size_t)(2 * vpp) * C3 + vn0;
        va = *reinterpret_cast<const uint4*>(vp);
        vb = *reinterpret_cast<const uint4*>(vp + C3);
        const uint32_t* kw0 = reinterpret_cast<const uint32_t*>(&ku0);
        const uint32_t* kw1 = reinterpret_cast<const uint32_t*>(&ku1);
        const uint32_t* vwa = reinterpret_cast<const uint32_t*>(&va);
        const uint32_t* vwb = reinterpret_cast<const uint32_t*>(&vb);
#pragma unroll
        for (int i = 0; i < 4; i++) {
            sK[0][kb + i * 2]     = kw0[i];
            sK[0][kb + i * 2 + 1] = kw1[i];
            sV[0][vst[i]]     = __byte_perm(vwa[i], vwb[i], 0x5410);
            sV[0][vst[i] + 8] = __byte_perm(vwa[i], vwb[i], 0x7632);
        }
    }
    __syncthreads();

    for (int kt = 0; kt < 16; kt++) {
        const int s = kt & 1;
        if (kt + 1 < 16) {
            const __half* kp = kbase + (size_t)((kt + 1) * 64 + knr) * C3 + kq * 16;
            ku0 = *reinterpret_cast<const uint4*>(kp);
            ku1 = *reinterpret_cast<const uint4*>(kp + 8);
            const __half* vp = vbase + (size_t)((kt + 1) * 64 + 2 * vpp) * C3 + vn0;
            va = *reinterpret_cast<const uint4*>(vp);
            vb = *reinterpret_cast<const uint4*>(vp + C3);
        }

        float sacc[8][4];
#pragma unroll
        for (int nt = 0; nt < 8; nt++) {
#pragma unroll
            for (int i = 0; i < 4; i++) sacc[nt][i] = 0.f;
#pragma unroll
            for (int ks = 0; ks < 4; ks++) {
                uint32_t bfr[2];
                *reinterpret_cast<uint2*>(bfr) =
                    *reinterpret_cast<const uint2*>(&sK[s][ks * 512 + nt * 64 + lane * 2]);
                mma_f16(sacc[nt], af[ks], bfr);
            }
        }

        float m0 = -1e30f, m1 = -1e30f;
#pragma unroll
        for (int nt = 0; nt < 8; nt++) {
#pragma unroll
            for (int i = 0; i < 4; i++) sacc[nt][i] *= 0.125f;
            m0 = fmaxf(m0, fmaxf(sacc[nt][0], sacc[nt][1]));
            m1 = fmaxf(m1, fmaxf(sacc[nt][2], sacc[nt][3]));
        }
        m0 = fmaxf(m0, __shfl_xor_sync(0xffffffffu, m0, 1));
        m0 = fmaxf(m0, __shfl_xor_sync(0xffffffffu, m0, 2));
        m1 = fmaxf(m1, __shfl_xor_sync(0xffffffffu, m1, 1));
        m1 = fmaxf(m1, __shfl_xor_sync(0xffffffffu, m1, 2));
        const float mn0 = fmaxf(mrun0, m0), mn1 = fmaxf(mrun1, m1);
        const float al0 = __expf(mrun0 - mn0), al1 = __expf(mrun1 - mn1);
        mrun0 = mn0; mrun1 = mn1;

        float r0 = 0.f, r1 = 0.f;
#pragma unroll
        for (int nt = 0; nt < 8; nt++) {
            sacc[nt][0] = __expf(sacc[nt][0] - mn0);
            sacc[nt][1] = __expf(sacc[nt][1] - mn0);
            sacc[nt][2] = __expf(sacc[nt][2] - mn1);
            sacc[nt][3] = __expf(sacc[nt][3] - mn1);
            r0 += sacc[nt][0] + sacc[nt][1];
            r1 += sacc[nt][2] + sacc[nt][3];
        }
        r0 += __shfl_xor_sync(0xffffffffu, r0, 1);
        r0 += __shfl_xor_sync(0xffffffffu, r0, 2);
        r1 += __shfl_xor_sync(0xffffffffu, r1, 1);
        r1 += __shfl_xor_sync(0xffffffffu, r1, 2);
        lrun0 = lrun0 * al0 + r0;
        lrun1 = lrun1 * al1 + r1;

#pragma unroll
        for (int nt = 0; nt < 8; nt++) {
            oacc[nt][0] *= al0; oacc[nt][1] *= al0;
            oacc[nt][2] *= al1; oacc[nt][3] *= al1;
        }

        uint32_t pf[4][4];
#pragma unroll
        for (int ks = 0; ks < 4; ks++) {
            pf[ks][0] = h2pack(sacc[2 * ks][0],     sacc[2 * ks][1]);
            pf[ks][1] = h2pack(sacc[2 * ks][2],     sacc[2 * ks][3]);
            pf[ks][2] = h2pack(sacc[2 * ks + 1][0], sacc[2 * ks + 1][1]);
            pf[ks][3] = h2pack(sacc[2 * ks + 1][2], sacc[2 * ks + 1][3]);
        }
#pragma unroll
        for (int nt = 0; nt < 8; nt++) {
#pragma unroll
            for (int ks = 0; ks < 4; ks++) {
                uint32_t bfr[2];
                *reinterpret_cast<uint2*>(bfr) =
                    *reinterpret_cast<const uint2*>(&sV[s][ks * 512 + nt * 64 + lane * 2]);
                mma_f16(oacc[nt], pf[ks], bfr);
            }
        }

        if (kt + 1 < 16) {
            const int ns = s ^ 1;
            const uint32_t* kw0 = reinterpret_cast<const uint32_t*>(&ku0);
            const uint32_t* kw1 = reinterpret_cast<const uint32_t*>(&ku1);
            const uint32_t* vwa = reinterpret_cast<const uint32_t*>(&va);
            const uint32_t* vwb = reinterpret_cast<const uint32_t*>(&vb);
#pragma unroll
            for (int i = 0; i < 4; i++) {
                sK[ns][kb + i * 2]     = kw0[i];
                sK[ns][kb + i * 2 + 1] = kw1[i];
                sV[ns][vst[i]]     = __byte_perm(vwa[i], vwb[i], 0x5410);
                sV[ns][vst[i] + 8] = __byte_perm(vwa[i], vwb[i], 0x7632);
            }
        }
        __syncthreads();
    }

    // epilogue -> A-fragment-tiled y (KB = 64)
    const float inv0 = 1.f / lrun0, inv1 = 1.f / lrun1;
    const int rowA = b * NT + qt * 128 + warp * 16 + (lane >> 2);
    const int colb = h * NHD + (lane & 3) * 2;
#pragma unroll
    for (int nt = 0; nt < 8; nt++) {
        yt[a_widx(rowA,     colb + nt * 8, 64)] =
            h2pack(oacc[nt][0] * inv0, oacc[nt][1] * inv0);
        yt[a_widx(rowA + 8, colb + nt * 8, 64)] =
            h2pack(oacc[nt][2] * inv1, oacc[nt][3] * inv1);
    }
}

// ---------------- host orchestration -----------------------------------------
#define SMEM_HG 65536

extern "C" void kernel_launch(void* const* d_in, const int* in_sizes, int n_in,
                              void* d_out, int out_size) {
    const int*   ids    = (const int*)  d_in[0];
    const float* wte    = (const float*)d_in[1];
    const float* wpe    = (const float*)d_in[2];
    const float* ln1_w  = (const float*)d_in[3];
    const float* ln1_b  = (const float*)d_in[4];
    const float* attn_w = (const float*)d_in[5];
    const float* attn_b = (const float*)d_in[6];
    const float* proj_w = (const float*)d_in[7];
    const float* proj_b = (const float*)d_in[8];
    const float* ln2_w  = (const float*)d_in[9];
    const float* ln2_b  = (const float*)d_in[10];
    const float* fc_w   = (const float*)d_in[11];
    const float* fc_b   = (const float*)d_in[12];
    const float* fc2_w  = (const float*)d_in[13];
    const float* fc2_b  = (const float*)d_in[14];
    const float* lnf_w  = (const float*)d_in[15];
    const float* lnf_b  = (const float*)d_in[16];
    float* out = (float*)d_out;

    float* x;
    __half* qkv16;
    uint32_t *h16t, *y16t, *mlp16t, *wa, *wp, *wf, *wf2, *wv;
    cudaGetSymbolAddress((void**)&x,      g_x);
    cudaGetSymbolAddress((void**)&qkv16,  g_qkv16);
    cudaGetSymbolAddress((void**)&h16t,   g_h16t);
    cudaGetSymbolAddress((void**)&y16t,   g_y16t);
    cudaGetSymbolAddress((void**)&mlp16t, g_mlp16t);
    cudaGetSymbolAddress((void**)&wa,     w_attn_t);
    cudaGetSymbolAddress((void**)&wp,     w_proj_t);
    cudaGetSymbolAddress((void**)&wf,     w_fc_t);
    cudaGetSymbolAddress((void**)&wf2,    w_fc2_t);
    cudaGetSymbolAddress((void**)&wv,     w_wte_t);

    cudaFuncSetAttribute(hgemm_t<1>, cudaFuncAttributeMaxDynamicSharedMemorySize, SMEM_HG);
    cudaFuncSetAttribute(hgemm_t<2>, cudaFuncAttributeMaxDynamicSharedMemorySize, SMEM_HG);
    cudaFuncSetAttribute(hgemm_t<3>, cudaFuncAttributeMaxDynamicSharedMemorySize, SMEM_HG);
    cudaFuncSetAttribute(hgemm_t<4>, cudaFuncAttributeMaxDynamicSharedMemorySize, SMEM_HG);

    embed_kernel<<<NTOK, 256>>>(ids, wte, wpe, x);
    cvt_w_nn<<<dim3(C3 / 128, 64, NL), 256>>>(attn_w, wa, NC, C3);
    cvt_w_nn<<<dim3(NC / 128, 64, NL), 256>>>(proj_w, wp, NC, NC);
    cvt_w_nn<<<dim3(C4 / 128, 64, NL), 256>>>(fc_w, wf, NC, C4);
    cvt_w_nn<<<dim3(NC / 128, 256, NL), 256>>>(fc2_w, wf2, C4, NC);
    cvt_wte_nt<<<dim3(NVP / 128, 64), 256>>>(wte, wv);

    const size_t wa_s = (size_t)NC * C3 / 2, wp_s = (size_t)NC * NC / 2;
    const size_t wf_s = (size_t)NC * C4 / 2, wf2_s = (size_t)C4 * NC / 2;

    for (int l = 0; l < NL; l++) {
        ln_kernel<<<NTOK, 256>>>(x, ln1_w + (size_t)l * NC, ln1_b + (size_t)l * NC, h16t);
        hgemm_t<3><<<dim3(C3 / 128, NTOK / 128), 256, SMEM_HG>>>(
            h16t, wa + l * wa_s, attn_b + (size_t)l * C3, qkv16, C3, 64);
        flash_attn<<<dim3(NT / 128, NB * NH), 256>>>(qkv16, y16t);
        hgemm_t<1><<<dim3(NC / 128, NTOK / 128), 256, SMEM_HG>>>(
            y16t, wp + l * wp_s, proj_b + (size_t)l * NC, x, NC, 64);
        ln_kernel<<<NTOK, 256>>>(x, ln2_w + (size_t)l * NC, ln2_b + (size_t)l * NC, h16t);
        hgemm_t<2><<<dim3(C4 / 128, NTOK / 128), 256, SMEM_HG>>>(
            h16t, wf + l * wf_s, fc_b + (size_t)l * C4, mlp16t, C4, 64);
        hgemm_t<1><<<dim3(NC / 128, NTOK / 128), 256, SMEM_HG>>>(
            mlp16t, wf2 + l * wf2_s, fc2_b + (size_t)l * NC, x, NC, 256);
    }

    ln_kernel<<<NTOK, 256>>>(x, lnf_w, lnf_b, h16t);
    hgemm_t<4><<<dim3(NVP / 128, NTOK / 128), 256, SMEM_HG>>>(
        h16t, wv, nullptr, out, NV, 64);
}

// round 10
// speedup vs baseline: 7.7825x; 1.0397x over previous
#include <cuda_runtime.h>
#include <cuda_fp16.h>
#include <math.h>
#include <stdint.h>

// Problem dims
#define NL   8
#define NB   2
#define NT   1024
#define NC   1024
#define NH   16
#define NHD  64
#define NV   50257
#define NVP  50304          // padded to 393*128
#define NTOK 2048
#define C3   3072
#define C4   4096

// ---------------- scratch ----------------------------------------------------
__device__ float    g_x    [NTOK * NC];            // residual (fp32)
__device__ __half   g_qkv16[NTOK * C3];            // qkv (fp16 row-major, flash input)
__device__ uint32_t g_h16t [NTOK * NC / 2];        // LN out, A-fragment-tiled
__device__ uint32_t g_y16t [NTOK * NC / 2];        // attn out, A-tiled
__device__ uint32_t g_mlp16t[NTOK * C4 / 2];       // GELU out, A-tiled
// fragment-tiled fp16 weights (built once per launch)
__device__ uint32_t w_attn_t[(size_t)NL * NC * C3 / 2];
__device__ uint32_t w_proj_t[(size_t)NL * NC * NC / 2];
__device__ uint32_t w_fc_t  [(size_t)NL * NC * C4 / 2];
__device__ uint32_t w_fc2_t [(size_t)NL * C4 * NC / 2];
__device__ uint32_t w_wte_t [(size_t)NVP * NC / 2];

// ---------------- helpers ----------------------------------------------------
__device__ __forceinline__ void mma_f16(float* d, const uint32_t* a, const uint32_t* b) {
    asm volatile(
        "mma.sync.aligned.m16n8k16.row.col.f32.f16.f16.f32 "
        "{%0,%1,%2,%3}, {%4,%5,%6,%7}, {%8,%9}, {%0,%1,%2,%3};"
        : "+f"(d[0]), "+f"(d[1]), "+f"(d[2]), "+f"(d[3])
        : "r"(a[0]), "r"(a[1]), "r"(a[2]), "r"(a[3]), "r"(b[0]), "r"(b[1]));
}
__device__ __forceinline__ uint32_t h2pack(float lo, float hi) {
    __half2 h = __floats2half2_rn(lo, hi);
    return *reinterpret_cast<uint32_t*>(&h);
}
__device__ __forceinline__ uint32_t smem_u32(const void* p) {
    uint32_t a;
    asm("{ .reg .u64 t; cvta.to.shared.u64 t, %1; cvt.u32.u64 %0, t; }" : "=r"(a) : "l"(p));
    return a;
}
#define CP_ASYNC16(dst, src) \
    asm volatile("cp.async.cg.shared.global [%0], [%1], 16;" :: "r"(dst), "l"(src))
#define CP_COMMIT() asm volatile("cp.async.commit_group;" ::: "memory")
#define CP_WAIT2()  asm volatile("cp.async.wait_group 2;" ::: "memory")

// A-fragment-tiled word index for pair (col even): word holds halves (col, col+1)
__device__ __forceinline__ size_t a_widx(int row, int col, int KB) {
    return ((size_t)(row >> 7) * KB + (col >> 4)) * 1024
         + ((row >> 4) & 7) * 128 + (row & 7) * 16 + ((row >> 3) & 1)
         + ((col >> 1) & 3) * 4 + ((col >> 3) & 1) * 2;
}

__device__ __forceinline__ float block_sum(float v) {
    __shared__ float sh[8];
    int lane = threadIdx.x & 31, w = threadIdx.x >> 5;
#pragma unroll
    for (int o = 16; o; o >>= 1) v += __shfl_xor_sync(0xffffffffu, v, o);
    if (lane == 0) sh[w] = v;
    __syncthreads();
    v = sh[0] + sh[1] + sh[2] + sh[3] + sh[4] + sh[5] + sh[6] + sh[7];
    __syncthreads();
    return v;
}

// ---------------- unified weight conversion (ONE launch) ----------------------
// segments: attn 12288 | proj 4096 | fc 16384 | fc2 16384 | wte 25152 = 74304
__global__ void __launch_bounds__(256) cvt_all(
    const float* __restrict__ attn_w, const float* __restrict__ proj_w,
    const float* __restrict__ fc_w,   const float* __restrict__ fc2_w,
    const float* __restrict__ wte,
    uint32_t* __restrict__ wa, uint32_t* __restrict__ wp,
    uint32_t* __restrict__ wf, uint32_t* __restrict__ wf2,
    uint32_t* __restrict__ wv)
{
    const int bid = blockIdx.x;
    const int t = threadIdx.x;
    if (bid < 49152) {  // NN tensors: in[k][n] -> [l][ntile][kblock][1024]
        const float* src; uint32_t* dst; int K, N, l, nt, kb;
        if (bid < 12288) {
            K = NC; N = C3; int id = bid;
            kb = id & 63; nt = (id >> 6) % 24; l = (id >> 6) / 24;
            src = attn_w; dst = wa;
        } else if (bid < 16384) {
            K = NC; N = NC; int id = bid - 12288;
            kb = id & 63; nt = (id >> 6) & 7; l = id >> 9;
            src = proj_w; dst = wp;
        } else if (bid < 32768) {
            K = NC; N = C4; int id = bid - 16384;
            kb = id & 63; nt = (id >> 6) & 31; l = id >> 11;
            src = fc_w; dst = wf;
        } else {
            K = C4; N = NC; int id = bid - 32768;
            kb = id & 255; nt = (id >> 8) & 7; l = id >> 11;
            src = fc2_w; dst = wf2;
        }
        const float* s = src + (size_t)l * K * N;
        uint32_t* d = dst + (((size_t)l * (N >> 7) + nt) * (K >> 4) + kb) * 1024;
#pragma unroll
        for (int w = 0; w < 4; w++) {
            int wid = t + 256 * w;
            int jj = wid >> 7, n = wid & 127;
            int k = kb * 16 + 2 * jj;
            int gn = nt * 128 + n;
            float lo = s[(size_t)k * N + gn];
            float hi = s[(size_t)(k + 1) * N + gn];
            d[(n >> 3) * 64 + (n & 7) * 8 + (jj & 3) * 2 + (jj >> 2)] = h2pack(lo, hi);
        }
    } else {            // wte NT: in[n][k] -> [ntile][kblock][1024], zero-padded
        int id = bid - 49152;
        int kb = id & 63, nt = id >> 6;
        uint32_t* d = wv + ((size_t)nt * 64 + kb) * 1024;
#pragma unroll
        for (int w = 0; w < 4; w++) {
            int wid = t + 256 * w;
            int nr = wid >> 3, jj = wid & 7;
            int gn = nt * 128 + nr;
            int k = kb * 16 + 2 * jj;
            float lo = 0.f, hi = 0.f;
            if (gn < NV) {
                lo = wte[(size_t)gn * NC + k];
                hi = wte[(size_t)gn * NC + k + 1];
            }
            d[(nr >> 3) * 64 + (nr & 7) * 8 + (jj & 3) * 2 + (jj >> 2)] = h2pack(lo, hi);
        }
    }
}

// ---------------- embedding / layernorm --------------------------------------
__global__ void embed_kernel(const int* __restrict__ ids,
                             const float* __restrict__ wte,
                             const float* __restrict__ wpe,
                             float* __restrict__ x) {
    int tok = blockIdx.x, t = tok & (NT - 1), id = ids[tok];
    const float* src = wte + (size_t)id * NC;
    const float* pp  = wpe + (size_t)t * NC;
    float* dst = x + (size_t)tok * NC;
    for (int c = threadIdx.x; c < NC; c += blockDim.x) dst[c] = src[c] + pp[c];
}

// layernorm -> A-fragment-tiled fp16 (KB = 64 for K=1024)
__global__ void __launch_bounds__(256) ln_kernel(const float* __restrict__ x,
                                                 const float* __restrict__ w,
                                                 const float* __restrict__ b,
                                                 uint32_t* __restrict__ o) {
    int row = blockIdx.x, tid = threadIdx.x;
    const float2* xr = reinterpret_cast<const float2*>(x + (size_t)row * NC);
    float2 v[2]; float s = 0.f;
#pragma unroll
    for (int i = 0; i < 2; i++) { v[i] = xr[tid + 256 * i]; s += v[i].x + v[i].y; }
    s = block_sum(s);
    float mean = s * (1.f / NC), s2 = 0.f;
#pragma unroll
    for (int i = 0; i < 2; i++) {
        float dx = v[i].x - mean, dy = v[i].y - mean;
        s2 += dx * dx + dy * dy;
    }
    s2 = block_sum(s2);
    float rstd = rsqrtf(s2 * (1.f / NC) + 1e-5f);
#pragma unroll
    for (int i = 0; i < 2; i++) {
        int col = 2 * (tid + 256 * i);
        float a0 = (v[i].x - mean) * rstd * w[col] + b[col];
        float a1 = (v[i].y - mean) * rstd * w[col + 1] + b[col + 1];
        o[a_widx(row, col, 64)] = h2pack(a0, a1);
    }
}

// =============================================================================
// Unified fragment-tiled FP16 GEMM with cp.async 4-stage pipeline (128x128 tile).
// EPI: 1 fp32 residual add (+bias)   2 GELU -> tiled fp16 (+bias)
//      3 fp16 row-major (+bias)      4 fp32 store, no bias, col<N guard
// =============================================================================
template <int EPI>
__global__ void __launch_bounds__(256) hgemm_t(const uint32_t* __restrict__ At,
                                               const uint32_t* __restrict__ Bt,
                                               const float* __restrict__ bias,
                                               void* __restrict__ Dv,
                                               int N, int KB) {
    extern __shared__ uint32_t dsm[];
    const int tid = threadIdx.x, lane = tid & 31, warp = tid >> 5;
    const int wm = warp >> 2, wn = warp & 3;
    const int bx = blockIdx.x, by = blockIdx.y;
    const uint32_t sb = smem_u32(dsm);

    const uint32_t* Asrc = At + (size_t)by * KB * 1024;
    const uint32_t* Bsrc = Bt + (size_t)bx * KB * 1024;
    const int KT = KB >> 1;

    auto issue = [&](int st, int kt2) {
        uint32_t d = sb + st * 16384 + tid * 16;
        const uint32_t* sa = Asrc + (size_t)kt2 * 2048 + tid * 4;
        const uint32_t* sbp = Bsrc + (size_t)kt2 * 2048 + tid * 4;
        CP_ASYNC16(d,         sa);
        CP_ASYNC16(d + 4096,  sa + 1024);
        CP_ASYNC16(d + 8192,  sbp);
        CP_ASYNC16(d + 12288, sbp + 1024);
    };

    for (int p = 0; p < 3; p++) { if (p < KT) issue(p, p); CP_COMMIT(); }

    float acc[4][4][4];
#pragma unroll
    for (int i = 0; i < 4; i++)
#pragma unroll
        for (int j = 0; j < 4; j++)
#pragma unroll
            for (int r = 0; r < 4; r++) acc[i][j][r] = 0.f;

    for (int kt = 0; kt < KT; kt++) {
        const int st = kt & 3;
        CP_WAIT2();
        __syncthreads();
        if (kt + 3 < KT) issue((kt + 3) & 3, kt + 3);
        CP_COMMIT();
#pragma unroll
        for (int s2 = 0; s2 < 2; s2++) {
            const uint32_t* As = dsm + st * 4096 + s2 * 1024;
            const uint32_t* Bs = dsm + st * 4096 + 2048 + s2 * 1024;
            uint32_t af[4][4], bf[4][2];
#pragma unroll
            for (int mt = 0; mt < 4; mt++)
                *reinterpret_cast<uint4*>(af[mt]) =
                    *reinterpret_cast<const uint4*>(&As[(wm * 4 + mt) * 128 + lane * 4]);
#pragma unroll
            for (int nt = 0; nt < 4; nt++)
                *reinterpret_cast<uint2*>(bf[nt]) =
                    *reinterpret_cast<const uint2*>(&Bs[(wn * 4 + nt) * 64 + lane * 2]);
#pragma unroll
            for (int mt = 0; mt < 4; mt++)
#pragma unroll
                for (int nt = 0; nt < 4; nt++)
                    mma_f16(acc[mt][nt], af[mt], bf[nt]);
        }
    }

#pragma unroll
    for (int mt = 0; mt < 4; mt++) {
        const int row0 = by * 128 + wm * 64 + mt * 16 + (lane >> 2);
#pragma unroll
        for (int nt = 0; nt < 4; nt++) {
            const int col0 = bx * 128 + wn * 32 + nt * 8 + (lane & 3) * 2;
#pragma unroll
            for (int hf = 0; hf < 2; hf++) {
                const int row = row0 + hf * 8;
                float v0 = acc[mt][nt][hf * 2 + 0];
                float v1 = acc[mt][nt][hf * 2 + 1];
                if (EPI != 4) { v0 += bias[col0]; v1 += bias[col0 + 1]; }
                if (EPI == 1) {
                    float* drow = (float*)Dv + (size_t)row * N + col0;
                    drow[0] += v0; drow[1] += v1;
                } else if (EPI == 2) {
                    v0 = 0.5f * v0 * (1.f + erff(v0 * 0.70710678118654752f));
                    v1 = 0.5f * v1 * (1.f + erff(v1 * 0.70710678118654752f));
                    ((uint32_t*)Dv)[a_widx(row, col0, N >> 4)] = h2pack(v0, v1);
                } else if (EPI == 3) {
                    __half* drow = (__half*)Dv + (size_t)row * N + col0;
                    *reinterpret_cast<__half2*>(drow) = __floats2half2_rn(v0, v1);
                } else {
                    float* drow = (float*)Dv + (size_t)row * N;
                    if (col0 < N)     drow[col0]     = v0;
                    if (col0 + 1 < N) drow[col0 + 1] = v1;
                }
            }
        }
    }
}

// =============================================================================
// 64x128-tile variant (EPI=1 residual only) for slot-starved GEMMs (proj, fc2).
// Warp tile 32x32; stage = A 1024 + B 2048 words = 12KB; 4 stages = 48KB.
// Same per-element K-order as hgemm_t -> bit-identical results.
// =============================================================================
__global__ void __launch_bounds__(256) hgemm_t64(const uint32_t* __restrict__ At,
                                                 const uint32_t* __restrict__ Bt,
                                                 const float* __restrict__ bias,
                                                 float* __restrict__ D,
                                                 int N, int KB) {
    extern __shared__ uint32_t dsm[];
    const int tid = threadIdx.x, lane = tid & 31, warp = tid >> 5;
    const int wm = warp >> 2, wn = warp & 3;   // wm 0..1, wn 0..3
    const int bx = blockIdx.x, by = blockIdx.y;
    const uint32_t sb = smem_u32(dsm);

    const uint32_t* Asrc = At + (size_t)(by >> 1) * KB * 1024 + (by & 1) * 512;
    const uint32_t* Bsrc = Bt + (size_t)bx * KB * 1024;
    const int KT = KB >> 1;

    const int aks = tid >> 7;            // which k16 of the stage this thread's A copy serves
    const int aw  = (tid & 127) * 4;     // word offset within 512-word half-block

    auto issue = [&](int st, int kt2) {
        uint32_t d = sb + st * 12288;
        const uint32_t* sa = Asrc + (size_t)(kt2 * 2 + aks) * 1024 + aw;
        CP_ASYNC16(d + tid * 16, sa);                     // A: words [0,1024)
        const uint32_t* sbp = Bsrc + (size_t)kt2 * 2048 + tid * 4;
        CP_ASYNC16(d + 4096 + tid * 16, sbp);             // B k16#0: words [1024,2048)
        CP_ASYNC16(d + 8192 + tid * 16, sbp + 1024);      // B k16#1: words [2048,3072)
    };

    for (int p = 0; p < 3; p++) { if (p < KT) issue(p, p); CP_COMMIT(); }

    float acc[2][4][4];
#pragma unroll
    for (int i = 0; i < 2; i++)
#pragma unroll
        for (int j = 0; j < 4; j++)
#pragma unroll
            for (int r = 0; r < 4; r++) acc[i][j][r] = 0.f;

    for (int kt = 0; kt < KT; kt++) {
        const int st = kt & 3;
        CP_WAIT2();
        __syncthreads();
        if (kt + 3 < KT) issue((kt + 3) & 3, kt + 3);
        CP_COMMIT();
#pragma unroll
        for (int s2 = 0; s2 < 2; s2++) {
            const uint32_t* As = dsm + st * 3072 + s2 * 512;
            const uint32_t* Bs = dsm + st * 3072 + 1024 + s2 * 1024;
            uint32_t af[2][4], bf[4][2];
#pragma unroll
            for (int mt = 0; mt < 2; mt++)
                *reinterpret_cast<uint4*>(af[mt]) =
                    *reinterpret_cast<const uint4*>(&As[(wm * 2 + mt) * 128 + lane * 4]);
#pragma unroll
            for (int nt = 0; nt < 4; nt++)
                *reinterpret_cast<uint2*>(bf[nt]) =
                    *reinterpret_cast<const uint2*>(&Bs[(wn * 4 + nt) * 64 + lane * 2]);
#pragma unroll
            for (int mt = 0; mt < 2; mt++)
#pragma unroll
                for (int nt = 0; nt < 4; nt++)
                    mma_f16(acc[mt][nt], af[mt], bf[nt]);
        }
    }

#pragma unroll
    for (int mt = 0; mt < 2; mt++) {
        const int row0 = by * 64 + wm * 32 + mt * 16 + (lane >> 2);
#pragma unroll
        for (int nt = 0; nt < 4; nt++) {
            const int col0 = bx * 128 + wn * 32 + nt * 8 + (lane & 3) * 2;
#pragma unroll
            for (int hf = 0; hf < 2; hf++) {
                const int row = row0 + hf * 8;
                float* drow = D + (size_t)row * N + col0;
                drow[0] += acc[mt][nt][hf * 2 + 0] + bias[col0];
                drow[1] += acc[mt][nt][hf * 2 + 1] + bias[col0 + 1];
            }
        }
    }
}

// =============================================================================
// Flash attention (fp16 MMA, fp32 softmax/accum) — tiled y out.
// =============================================================================
__global__ void __launch_bounds__(256) flash_attn(const __half* __restrict__ qkv,
                                                  uint32_t* __restrict__ yt) {
    __shared__ uint32_t sK[2][2048];
    __shared__ uint32_t sV[2][2048];
    uint32_t* sq = &sK[0][0];

    const int tid = threadIdx.x, lane = tid & 31, warp = tid >> 5;
    const int qt = blockIdx.x;
    const int bh = blockIdx.y, b = bh >> 4, h = bh & 15;

    const __half* qbase = qkv + (size_t)(b * NT + qt * 128) * C3 + h * NHD;
    const __half* kbase = qkv + (size_t)(b * NT) * C3 + NC + h * NHD;
    const __half* vbase = qkv + (size_t)(b * NT) * C3 + 2 * NC + h * NHD;

    uint32_t af[4][4];
    {
        const int r = tid >> 1, hfq = tid & 1;
        const __half* qp = qbase + (size_t)r * C3 + hfq * 32;
        uint4 v0 = *reinterpret_cast<const uint4*>(qp);
        uint4 v1 = *reinterpret_cast<const uint4*>(qp + 8);
        uint4 v2 = *reinterpret_cast<const uint4*>(qp + 16);
        uint4 v3 = *reinterpret_cast<const uint4*>(qp + 24);
        const int ab0 = (2 * hfq) * 1024 + (r >> 4) * 128 + (r & 7) * 16 + ((r >> 3) & 1);
        const int ab1 = ab0 + 1024;
        const uint32_t* w0 = reinterpret_cast<const uint32_t*>(&v0);
        const uint32_t* w1 = reinterpret_cast<const uint32_t*>(&v1);
        const uint32_t* w2 = reinterpret_cast<const uint32_t*>(&v2);
        const uint32_t* w3 = reinterpret_cast<const uint32_t*>(&v3);
#pragma unroll
        for (int i = 0; i < 4; i++) {
            sq[ab0 + i * 4]     = w0[i];
            sq[ab0 + i * 4 + 2] = w1[i];
            sq[ab1 + i * 4]     = w2[i];
            sq[ab1 + i * 4 + 2] = w3[i];
        }
        __syncthreads();
#pragma unroll
        for (int ks = 0; ks < 4; ks++)
            *reinterpret_cast<uint4*>(af[ks]) =
                *reinterpret_cast<const uint4*>(&sq[ks * 1024 + warp * 128 + lane * 4]);
        __syncthreads();
    }

    const int knr = tid >> 2, kq = tid & 3;
    const int kb  = kq * 512 + (knr >> 3) * 64 + (knr & 7) * 8;
    const int vpp = tid >> 3, vn0 = (tid & 7) * 8;
    const int vks = vpp >> 3, vjj = vpp & 7;
    int vst[4];
#pragma unroll
    for (int i = 0; i < 4; i++) {
        int n = vn0 + 2 * i;
        vst[i] = vks * 512 + (n >> 3) * 64 + ((n & 7) * 4 + (vjj & 3)) * 2 + (vjj >> 2);
    }

    float oacc[8][4];
#pragma unroll
    for (int nt = 0; nt < 8; nt++)
#pragma unroll
        for (int i = 0; i < 4; i++) oacc[nt][i] = 0.f;
    float mrun0 = -1e30f, mrun1 = -1e30f, lrun0 = 0.f, lrun1 = 0.f;

    uint4 ku0, ku1, va, vb;
    {
        const __half* kp = kbase + (size_t)knr * C3 + kq * 16;
        ku0 = *reinterpret_cast<const uint4*>(kp);
        ku1 = *reinterpret_cast<const uint4*>(kp + 8);
        const __half* vp = vbase + (size_t)(2 * vpp) * C3 + vn0;
        va = *reinterpret_cast<const uint4*>(vp);
        vb = *reinterpret_cast<const uint4*>(vp + C3);
        const uint32_t* kw0 = reinterpret_cast<const uint32_t*>(&ku0);
        const uint32_t* kw1 = reinterpret_cast<const uint32_t*>(&ku1);
        const uint32_t* vwa = reinterpret_cast<const uint32_t*>(&va);
        const uint32_t* vwb = reinterpret_cast<const uint32_t*>(&vb);
#pragma unroll
        for (int i = 0; i < 4; i++) {
            sK[0][kb + i * 2]     = kw0[i];
            sK[0][kb + i * 2 + 1] = kw1[i];
            sV[0][vst[i]]     = __byte_perm(vwa[i], vwb[i], 0x5410);
            sV[0][vst[i] + 8] = __byte_perm(vwa[i], vwb[i], 0x7632);
        }
    }
    __syncthreads();

    for (int kt = 0; kt < 16; kt++) {
        const int s = kt & 1;
        if (kt + 1 < 16) {
            const __half* kp = kbase + (size_t)((kt + 1) * 64 + knr) * C3 + kq * 16;
            ku0 = *reinterpret_cast<const uint4*>(kp);
            ku1 = *reinterpret_cast<const uint4*>(kp + 8);
            const __half* vp = vbase + (size_t)((kt + 1) * 64 + 2 * vpp) * C3 + vn0;
            va = *reinterpret_cast<const uint4*>(vp);
            vb = *reinterpret_cast<const uint4*>(vp + C3);
        }

        float sacc[8][4];
#pragma unroll
        for (int nt = 0; nt < 8; nt++) {
#pragma unroll
            for (int i = 0; i < 4; i++) sacc[nt][i] = 0.f;
#pragma unroll
            for (int ks = 0; ks < 4; ks++) {
                uint32_t bfr[2];
                *reinterpret_cast<uint2*>(bfr) =
                    *reinterpret_cast<const uint2*>(&sK[s][ks * 512 + nt * 64 + lane * 2]);
                mma_f16(sacc[nt], af[ks], bfr);
            }
        }

        float m0 = -1e30f, m1 = -1e30f;
#pragma unroll
        for (int nt = 0; nt < 8; nt++) {
#pragma unroll
            for (int i = 0; i < 4; i++) sacc[nt][i] *= 0.125f;
            m0 = fmaxf(m0, fmaxf(sacc[nt][0], sacc[nt][1]));
            m1 = fmaxf(m1, fmaxf(sacc[nt][2], sacc[nt][3]));
        }
        m0 = fmaxf(m0, __shfl_xor_sync(0xffffffffu, m0, 1));
        m0 = fmaxf(m0, __shfl_xor_sync(0xffffffffu, m0, 2));
        m1 = fmaxf(m1, __shfl_xor_sync(0xffffffffu, m1, 1));
        m1 = fmaxf(m1, __shfl_xor_sync(0xffffffffu, m1, 2));
        const float mn0 = fmaxf(mrun0, m0), mn1 = fmaxf(mrun1, m1);
        const float al0 = __expf(mrun0 - mn0), al1 = __expf(mrun1 - mn1);
        mrun0 = mn0; mrun1 = mn1;

        float r0 = 0.f, r1 = 0.f;
#pragma unroll
        for (int nt = 0; nt < 8; nt++) {
            sacc[nt][0] = __expf(sacc[nt][0] - mn0);
            sacc[nt][1] = __expf(sacc[nt][1] - mn0);
            sacc[nt][2] = __expf(sacc[nt][2] - mn1);
            sacc[nt][3] = __expf(sacc[nt][3] - mn1);
            r0 += sacc[nt][0] + sacc[nt][1];
            r1 += sacc[nt][2] + sacc[nt][3];
        }
        r0 += __shfl_xor_sync(0xffffffffu, r0, 1);
        r0 += __shfl_xor_sync(0xffffffffu, r0, 2);
        r1 += __shfl_xor_sync(0xffffffffu, r1, 1);
        r1 += __shfl_xor_sync(0xffffffffu, r1, 2);
        lrun0 = lrun0 * al0 + r0;
        lrun1 = lrun1 * al1 + r1;

#pragma unroll
        for (int nt = 0; nt < 8; nt++) {
            oacc[nt][0] *= al0; oacc[nt][1] *= al0;
            oacc[nt][2] *= al1; oacc[nt][3] *= al1;
        }

        uint32_t pf[4][4];
#pragma unroll
        for (int ks = 0; ks < 4; ks++) {
            pf[ks][0] = h2pack(sacc[2 * ks][0],     sacc[2 * ks][1]);
            pf[ks][1] = h2pack(sacc[2 * ks][2],     sacc[2 * ks][3]);
            pf[ks][2] = h2pack(sacc[2 * ks + 1][0], sacc[2 * ks + 1][1]);
            pf[ks][3] = h2pack(sacc[2 * ks + 1][2], sacc[2 * ks + 1][3]);
        }
#pragma unroll
        for (int nt = 0; nt < 8; nt++) {
#pragma unroll
            for (int ks = 0; ks < 4; ks++) {
                uint32_t bfr[2];
                *reinterpret_cast<uint2*>(bfr) =
                    *reinterpret_cast<const uint2*>(&sV[s][ks * 512 + nt * 64 + lane * 2]);
                mma_f16(oacc[nt], pf[ks], bfr);
            }
        }

        if (kt + 1 < 16) {
            const int ns = s ^ 1;
            const uint32_t* kw0 = reinterpret_cast<const uint32_t*>(&ku0);
            const uint32_t* kw1 = reinterpret_cast<const uint32_t*>(&ku1);
            const uint32_t* vwa = reinterpret_cast<const uint32_t*>(&va);
            const uint32_t* vwb = reinterpret_cast<const uint32_t*>(&vb);
#pragma unroll
            for (int i = 0; i < 4; i++) {
                sK[ns][kb + i * 2]     = kw0[i];
                sK[ns][kb + i * 2 + 1] = kw1[i];
                sV[ns][vst[i]]     = __byte_perm(vwa[i], vwb[i], 0x5410);
                sV[ns][vst[i] + 8] = __byte_perm(vwa[i], vwb[i], 0x7632);
            }
        }
        __syncthreads();
    }

    const float inv0 = 1.f / lrun0, inv1 = 1.f / lrun1;
    const int rowA = b * NT + qt * 128 + warp * 16 + (lane >> 2);
    const int colb = h * NHD + (lane & 3) * 2;
#pragma unroll
    for (int nt = 0; nt < 8; nt++) {
        yt[a_widx(rowA,     colb + nt * 8, 64)] =
            h2pack(oacc[nt][0] * inv0, oacc[nt][1] * inv0);
        yt[a_widx(rowA + 8, colb + nt * 8, 64)] =
            h2pack(oacc[nt][2] * inv1, oacc[nt][3] * inv1);
    }
}

// ---------------- host orchestration -----------------------------------------
#define SMEM_HG   65536
#define SMEM_HG64 49152

extern "C" void kernel_launch(void* const* d_in, const int* in_sizes, int n_in,
                              void* d_out, int out_size) {
    const int*   ids    = (const int*)  d_in[0];
    const float* wte    = (const float*)d_in[1];
    const float* wpe    = (const float*)d_in[2];
    const float* ln1_w  = (const float*)d_in[3];
    const float* ln1_b  = (const float*)d_in[4];
    const float* attn_w = (const float*)d_in[5];
    const float* attn_b = (const float*)d_in[6];
    const float* proj_w = (const float*)d_in[7];
    const float* proj_b = (const float*)d_in[8];
    const float* ln2_w  = (const float*)d_in[9];
    const float* ln2_b  = (const float*)d_in[10];
    const float* fc_w   = (const float*)d_in[11];
    const float* fc_b   = (const float*)d_in[12];
    const float* fc2_w  = (const float*)d_in[13];
    const float* fc2_b  = (const float*)d_in[14];
    const float* lnf_w  = (const float*)d_in[15];
    const float* lnf_b  = (const float*)d_in[16];
    float* out = (float*)d_out;

    float* x;
    __half* qkv16;
    uint32_t *h16t, *y16t, *mlp16t, *wa, *wp, *wf, *wf2, *wv;
    cudaGetSymbolAddress((void**)&x,      g_x);
    cudaGetSymbolAddress((void**)&qkv16,  g_qkv16);
    cudaGetSymbolAddress((void**)&h16t,   g_h16t);
    cudaGetSymbolAddress((void**)&y16t,   g_y16t);
    cudaGetSymbolAddress((void**)&mlp16t, g_mlp16t);
    cudaGetSymbolAddress((void**)&wa,     w_attn_t);
    cudaGetSymbolAddress((void**)&wp,     w_proj_t);
    cudaGetSymbolAddress((void**)&wf,     w_fc_t);
    cudaGetSymbolAddress((void**)&wf2,    w_fc2_t);
    cudaGetSymbolAddress((void**)&wv,     w_wte_t);

    cudaFuncSetAttribute(hgemm_t<1>, cudaFuncAttributeMaxDynamicSharedMemorySize, SMEM_HG);
    cudaFuncSetAttribute(hgemm_t<2>, cudaFuncAttributeMaxDynamicSharedMemorySize, SMEM_HG);
    cudaFuncSetAttribute(hgemm_t<3>, cudaFuncAttributeMaxDynamicSharedMemorySize, SMEM_HG);
    cudaFuncSetAttribute(hgemm_t<4>, cudaFuncAttributeMaxDynamicSharedMemorySize, SMEM_HG);
    cudaFuncSetAttribute(hgemm_t64,  cudaFuncAttributeMaxDynamicSharedMemorySize, SMEM_HG64);

    embed_kernel<<<NTOK, 256>>>(ids, wte, wpe, x);
    cvt_all<<<74304, 256>>>(attn_w, proj_w, fc_w, fc2_w, wte, wa, wp, wf, wf2, wv);

    const size_t wa_s = (size_t)NC * C3 / 2, wp_s = (size_t)NC * NC / 2;
    const size_t wf_s = (size_t)NC * C4 / 2, wf2_s = (size_t)C4 * NC / 2;

    for (int l = 0; l < NL; l++) {
        ln_kernel<<<NTOK, 256>>>(x, ln1_w + (size_t)l * NC, ln1_b + (size_t)l * NC, h16t);
        hgemm_t<3><<<dim3(C3 / 128, NTOK / 128), 256, SMEM_HG>>>(
            h16t, wa + l * wa_s, attn_b + (size_t)l * C3, qkv16, C3, 64);
        flash_attn<<<dim3(NT / 128, NB * NH), 256>>>(qkv16, y16t);
        hgemm_t64<<<dim3(NC / 128, NTOK / 64), 256, SMEM_HG64>>>(
            y16t, wp + l * wp_s, proj_b + (size_t)l * NC, x, NC, 64);
        ln_kernel<<<NTOK, 256>>>(x, ln2_w + (size_t)l * NC, ln2_b + (size_t)l * NC, h16t);
        hgemm_t<2><<<dim3(C4 / 128, NTOK / 128), 256, SMEM_HG>>>(
            h16t, wf + l * wf_s, fc_b + (size_t)l * C4, mlp16t, C4, 64);
        hgemm_t64<<<dim3(NC / 128, NTOK / 64), 256, SMEM_HG64>>>(
            mlp16t, wf2 + l * wf2_s, fc2_b + (size_t)l * NC, x, NC, 256);
    }

    ln_kernel<<<NTOK, 256>>>(x, lnf_w, lnf_b, h16t);
    hgemm_t<4><<<dim3(NVP / 128, NTOK / 128), 256, SMEM_HG>>>(
        h16t, wv, nullptr, out, NV, 64);
}